// round 9
// baseline (speedup 1.0000x reference)
#include <cuda_runtime.h>
#include <cuda_bf16.h>
#include <cuda_fp16.h>
#include <math.h>
#include <stdint.h>

// Problem constants
#define BATCH   4
#define TSEQ    2048
#define DMODEL  1024
#define NHEADS  16
#define DHEAD   64
#define MTOK    (BATCH * TSEQ)       // 8192 rows
#define QKV_N   (3 * DMODEL)         // 3072

// Scratch (no cudaMalloc). All per-token layouts are [tok][1024] (h*64+d).
__device__ __nv_bfloat16 g_Qh[(size_t)MTOK * DMODEL];
__device__ __nv_bfloat16 g_Ql[(size_t)MTOK * DMODEL];
__device__ __nv_bfloat16 g_Kh[(size_t)MTOK * DMODEL];
__device__ __nv_bfloat16 g_Kl[(size_t)MTOK * DMODEL];
__device__ __half        g_Vh[(size_t)MTOK * DMODEL];
__device__ __nv_bfloat16 g_xh[(size_t)MTOK * DMODEL];
__device__ __nv_bfloat16 g_xl[(size_t)MTOK * DMODEL];
__device__ __nv_bfloat16 g_wqh[(size_t)DMODEL * QKV_N];
__device__ __nv_bfloat16 g_wql[(size_t)DMODEL * QKV_N];
__device__ __nv_bfloat16 g_woh[(size_t)DMODEL * DMODEL];
__device__ __nv_bfloat16 g_wol[(size_t)DMODEL * DMODEL];
__device__ __nv_bfloat16 g_ah[(size_t)MTOK * DMODEL];   // attention out hi/lo
__device__ __nv_bfloat16 g_al[(size_t)MTOK * DMODEL];

// ---------------------------------------------------------------------------
// PTX helpers
// ---------------------------------------------------------------------------
__device__ __forceinline__ uint32_t smem_u32(const void* p) {
    uint32_t a;
    asm("{ .reg .u64 t; cvta.to.shared.u64 t, %1; cvt.u32.u64 %0, t; }"
        : "=r"(a) : "l"(p));
    return a;
}
__device__ __forceinline__ void ldmx4(uint32_t* r, uint32_t addr) {
    asm volatile("ldmatrix.sync.aligned.m8n8.x4.shared.b16 {%0,%1,%2,%3}, [%4];"
                 : "=r"(r[0]), "=r"(r[1]), "=r"(r[2]), "=r"(r[3]) : "r"(addr));
}
__device__ __forceinline__ void ldmx4t(uint32_t* r, uint32_t addr) {
    asm volatile("ldmatrix.sync.aligned.m8n8.x4.trans.shared.b16 {%0,%1,%2,%3}, [%4];"
                 : "=r"(r[0]), "=r"(r[1]), "=r"(r[2]), "=r"(r[3]) : "r"(addr));
}
__device__ __forceinline__ void mma_bf(float* c, const uint32_t* a, const uint32_t* b) {
    asm volatile(
        "mma.sync.aligned.m16n8k16.row.col.f32.bf16.bf16.f32 "
        "{%0,%1,%2,%3}, {%4,%5,%6,%7}, {%8,%9}, {%0,%1,%2,%3};"
        : "+f"(c[0]), "+f"(c[1]), "+f"(c[2]), "+f"(c[3])
        : "r"(a[0]), "r"(a[1]), "r"(a[2]), "r"(a[3]), "r"(b[0]), "r"(b[1]));
}
__device__ __forceinline__ void mma_hf(float* c, const uint32_t* a, const uint32_t* b) {
    asm volatile(
        "mma.sync.aligned.m16n8k16.row.col.f32.f16.f16.f32 "
        "{%0,%1,%2,%3}, {%4,%5,%6,%7}, {%8,%9}, {%0,%1,%2,%3};"
        : "+f"(c[0]), "+f"(c[1]), "+f"(c[2]), "+f"(c[3])
        : "r"(a[0]), "r"(a[1]), "r"(a[2]), "r"(a[3]), "r"(b[0]), "r"(b[1]));
}
__device__ __forceinline__ uint32_t ex2_f16x2(uint32_t x) {
    uint32_t r;
    asm("ex2.approx.f16x2 %0, %1;" : "=r"(r) : "r"(x));
    return r;
}
__device__ __forceinline__ void cpa16(uint32_t dst, const void* src) {
    asm volatile("cp.async.cg.shared.global [%0], [%1], 16;" :: "r"(dst), "l"(src));
}
// SW128 swizzle for 128-byte-pitch rows (attention smem only)
__device__ __forceinline__ uint32_t sw128(int row, int byteoff) {
    return (uint32_t)(row * 128 + (byteoff ^ ((row & 7) << 4)));
}
__device__ __forceinline__ void bfsplit2(float a, float b, uint32_t& hi, uint32_t& lo) {
    __nv_bfloat162 h, l;
    h.x = __float2bfloat16_rn(a);
    h.y = __float2bfloat16_rn(b);
    l.x = __float2bfloat16_rn(a - __bfloat162float(h.x));
    l.y = __float2bfloat16_rn(b - __bfloat162float(h.y));
    hi = *(uint32_t*)&h;
    lo = *(uint32_t*)&l;
}

// ---------------------------------------------------------------------------
// fp32 -> bf16 hi/lo split
// ---------------------------------------------------------------------------
__global__ __launch_bounds__(256) void split_bf16(
    const float* __restrict__ in, __nv_bfloat16* __restrict__ hi,
    __nv_bfloat16* __restrict__ lo, int n4)
{
    int i = blockIdx.x * blockDim.x + threadIdx.x;
    if (i >= n4) return;
    float4 v = ((const float4*)in)[i];
    uint32_t h0, l0, h1, l1;
    bfsplit2(v.x, v.y, h0, l0);
    bfsplit2(v.z, v.w, h1, l1);
    ((uint2*)hi)[i] = make_uint2(h0, h1);
    ((uint2*)lo)[i] = make_uint2(l0, l1);
}

// ---------------------------------------------------------------------------
// Tensor-core GEMM, bf16 hi/lo 3-term. Single __syncthreads per K-chunk:
// iter c = { wait_group 0; sync; prefetch(c+1); mma(c) }.
// Safety: prefetch(c+1) writes buffer (c+1)&1, whose last readers (iter c-1)
// have all passed sync_c before any warp can issue the prefetch.
// MODE 0: qkv epilogue -> split into g_Qh/Ql/Kh/Kl/Vh ([tok][1024] each).
// MODE 1: plain fp32 C.
// ---------------------------------------------------------------------------
#define GPAD_A 40
#define GPAD_B 136
#define STAGE_A (128 * GPAD_A)
#define STAGE_B (32 * GPAD_B)
#define STAGE_ELEMS (2 * STAGE_A + 2 * STAGE_B)
#define GEMM_SMEM (2 * STAGE_ELEMS * 2)

template<int MODE>
__global__ __launch_bounds__(256, 2) void tc_gemm4(
    const __nv_bfloat16* __restrict__ Ah, const __nv_bfloat16* __restrict__ Al,
    const __nv_bfloat16* __restrict__ Bh, const __nv_bfloat16* __restrict__ Bl,
    float* __restrict__ C, int M, int N, int K)
{
    extern __shared__ __nv_bfloat16 sm[];
    const uint32_t smb = smem_u32(sm);

    const int tid  = threadIdx.x;
    const int lane = tid & 31;
    const int wid  = tid >> 5;
    const int wm   = wid & 1;
    const int wn   = wid >> 1;
    const int crow = blockIdx.y * 128;
    const int ccol = blockIdx.x * 128;

    const int arow0 = tid >> 2;
    const int ach   = (tid & 3) * 8;
    const int brow0 = tid >> 4;
    const int bch   = (tid & 15) * 8;

    auto prefetch = [&](int c) {
        const uint32_t sb = smb + (uint32_t)(c & 1) * (STAGE_ELEMS * 2);
        const size_t ka = (size_t)c * 32;
        #pragma unroll
        for (int j = 0; j < 2; j++) {
            int row = arow0 + j * 64;
            const __nv_bfloat16* sh = Ah + (size_t)(crow + row) * K + ka + ach;
            const __nv_bfloat16* sl = Al + (size_t)(crow + row) * K + ka + ach;
            uint32_t d = sb + (uint32_t)(row * GPAD_A + ach) * 2;
            cpa16(d, sh);
            cpa16(d + STAGE_A * 2, sl);
        }
        #pragma unroll
        for (int j = 0; j < 2; j++) {
            int row = brow0 + j * 16;
            const __nv_bfloat16* sh = Bh + (ka + row) * N + ccol + bch;
            const __nv_bfloat16* sl = Bl + (ka + row) * N + ccol + bch;
            uint32_t d = sb + (uint32_t)(2 * STAGE_A + row * GPAD_B + bch) * 2;
            cpa16(d, sh);
            cpa16(d + STAGE_B * 2, sl);
        }
        asm volatile("cp.async.commit_group;" ::: "memory");
    };

    const int aRowBase = wm * 64 + (lane & 15);
    const int aColOff  = (lane >> 4) * 8;
    const int bKrow    = (lane & 7) + ((lane >> 3) & 1) * 8;
    const int bNBase   = wn * 32 + (lane >> 4) * 8;

    float acc[4][4][4];
    #pragma unroll
    for (int i = 0; i < 4; i++)
        #pragma unroll
        for (int j = 0; j < 4; j++)
            #pragma unroll
            for (int r = 0; r < 4; r++) acc[i][j][r] = 0.f;

    const int nchunks = K >> 5;
    prefetch(0);

    for (int c = 0; c < nchunks; c++) {
        asm volatile("cp.async.wait_group 0;" ::: "memory");
        __syncthreads();
        if (c + 1 < nchunks) prefetch(c + 1);

        const uint32_t sb  = smb + (uint32_t)(c & 1) * (STAGE_ELEMS * 2);
        const uint32_t bAh = sb;
        const uint32_t bAl = sb + STAGE_A * 2;
        const uint32_t bBh = sb + 2 * STAGE_A * 2;
        const uint32_t bBl = bBh + STAGE_B * 2;

        #pragma unroll
        for (int ks = 0; ks < 2; ks++) {
            uint32_t ah[4][4], al[4][4], bh[2][4], bl[2][4];
            #pragma unroll
            for (int mf = 0; mf < 4; mf++) {
                uint32_t off = (uint32_t)((aRowBase + mf * 16) * GPAD_A + ks * 16 + aColOff) * 2;
                ldmx4(ah[mf], bAh + off);
                ldmx4(al[mf], bAl + off);
            }
            #pragma unroll
            for (int nf2 = 0; nf2 < 2; nf2++) {
                uint32_t off = (uint32_t)((ks * 16 + bKrow) * GPAD_B + bNBase + nf2 * 16) * 2;
                ldmx4t(bh[nf2], bBh + off);
                ldmx4t(bl[nf2], bBl + off);
            }
            #pragma unroll
            for (int mf = 0; mf < 4; mf++)
                #pragma unroll
                for (int nf = 0; nf < 4; nf++) {
                    const uint32_t* bhp = &bh[nf >> 1][(nf & 1) * 2];
                    const uint32_t* blp = &bl[nf >> 1][(nf & 1) * 2];
                    mma_bf(acc[mf][nf], ah[mf], bhp);
                    mma_bf(acc[mf][nf], ah[mf], blp);
                    mma_bf(acc[mf][nf], al[mf], bhp);
                }
        }
    }

    if (MODE == 1) {
        #pragma unroll
        for (int mf = 0; mf < 4; mf++) {
            int row0 = crow + wm * 64 + mf * 16 + (lane >> 2);
            #pragma unroll
            for (int nf = 0; nf < 4; nf++) {
                int col = ccol + wn * 32 + nf * 8 + (lane & 3) * 2;
                *(float2*)&C[(size_t)row0 * N + col] =
                    make_float2(acc[mf][nf][0], acc[mf][nf][1]);
                *(float2*)&C[(size_t)(row0 + 8) * N + col] =
                    make_float2(acc[mf][nf][2], acc[mf][nf][3]);
            }
        }
    } else {
        const int nbase = ccol + wn * 32;
        const int sect  = nbase >> 10;
        #pragma unroll
        for (int mf = 0; mf < 4; mf++) {
            int m0 = crow + wm * 64 + mf * 16 + (lane >> 2);
            #pragma unroll
            for (int nf = 0; nf < 4; nf++) {
                int col = (nbase + nf * 8 + (lane & 3) * 2) & 1023;
                #pragma unroll
                for (int r2 = 0; r2 < 2; r2++) {
                    size_t di = (size_t)(m0 + r2 * 8) * 1024 + col;
                    float o0 = acc[mf][nf][r2 * 2], o1 = acc[mf][nf][r2 * 2 + 1];
                    if (sect == 2) {
                        __half2 hv = __floats2half2_rn(o0, o1);
                        *(__half2*)&g_Vh[di] = hv;
                    } else {
                        uint32_t hi, lo;
                        bfsplit2(o0, o1, hi, lo);
                        if (sect == 0) {
                            *(uint32_t*)&g_Qh[di] = hi;
                            *(uint32_t*)&g_Ql[di] = lo;
                        } else {
                            *(uint32_t*)&g_Kh[di] = hi;
                            *(uint32_t*)&g_Kl[di] = lo;
                        }
                    }
                }
            }
        }
    }
}

// ---------------------------------------------------------------------------
// Tensor-core causal flash attention, cp.async double-buffered KV tiles,
// single __syncthreads per kv tile (same hazard argument as the GEMM).
// smem: Qh 16K | Ql 16K | 2 x (Kh 8K | Kl 8K | V 8K) = 80 KB.
// ---------------------------------------------------------------------------
#define KV_STAGE 24576
#define ATTN_SMEM (32768 + 2 * KV_STAGE)

__global__ __launch_bounds__(256, 2) void flash_attn_tc4(
    const __nv_bfloat16* __restrict__ Qh, const __nv_bfloat16* __restrict__ Ql,
    const __nv_bfloat16* __restrict__ Kh, const __nv_bfloat16* __restrict__ Kl,
    const __half* __restrict__ Vh,
    __nv_bfloat16* __restrict__ oh, __nv_bfloat16* __restrict__ ol)
{
    extern __shared__ char smraw[];
    char* pQh = smraw;
    char* pQl = smraw + 16384;
    const uint32_t kvb = smem_u32(smraw + 32768);

    const int tid = threadIdx.x, lane = tid & 31, wid = tid >> 5;
    const int b  = blockIdx.y >> 4;
    const int h  = blockIdx.y & 15;
    const int qt = gridDim.x - 1 - blockIdx.x;   // heavy tiles first
    const int q0 = qt * 128;

    const size_t rbase = (size_t)b * 2048;
    const int    cbase = h * 64;

    auto prefetch_kv = [&](int kt) {
        const int kv0 = kt * 64;
        const uint32_t sb = kvb + (uint32_t)(kt & 1) * KV_STAGE;
        #pragma unroll
        for (int i = 0; i < 2; i++) {
            int li = i * 256 + tid;
            int r = li >> 3, ch = li & 7;
            size_t gi = (rbase + kv0 + r) * 1024 + cbase + ch * 8;
            uint32_t so = sw128(r, ch * 16);
            cpa16(sb + so,         Kh + gi);
            cpa16(sb + 8192 + so,  Kl + gi);
            cpa16(sb + 16384 + so, Vh + gi);
        }
        asm volatile("cp.async.commit_group;" ::: "memory");
    };

    prefetch_kv(0);

    // Load Q tiles (128 rows x 128B), swizzled (plain STS; covered by sync 0)
    #pragma unroll
    for (int i = 0; i < 4; i++) {
        int li = i * 256 + tid;
        int r = li >> 3, ch = li & 7;
        size_t gi = (rbase + q0 + r) * 1024 + cbase + ch * 8;
        uint32_t so = sw128(r, ch * 16);
        *(uint4*)(pQh + so) = *(const uint4*)(Qh + gi);
        *(uint4*)(pQl + so) = *(const uint4*)(Ql + gi);
    }

    const uint32_t aQh = smem_u32(pQh), aQl = smem_u32(pQl);

    const int rowQ = wid * 16 + (lane & 15);
    const int colB = (lane >> 4) * 16;              // bytes
    const int kRow = lane & 15;
    const int vRow = (lane & 7) + ((lane >> 3) & 1) * 8;

    float accO[8][4];
    #pragma unroll
    for (int i = 0; i < 8; i++)
        #pragma unroll
        for (int r = 0; r < 4; r++) accO[i][r] = 0.f;
    float lr = 0.f, lr8 = 0.f;

    const int rowbase = q0 + wid * 16;
    const int nkt = 2 * qt + 2;
    const float csc = 0.1803368802f;   // log2(e)/8

    for (int kt = 0; kt < nkt; kt++) {
        const int kv0 = kt * 64;
        asm volatile("cp.async.wait_group 0;" ::: "memory");
        __syncthreads();
        if (kt + 1 < nkt) prefetch_kv(kt + 1);

        const uint32_t sb  = kvb + (uint32_t)(kt & 1) * KV_STAGE;
        const uint32_t aKh = sb;
        const uint32_t aKl = sb + 8192;
        const uint32_t aV  = sb + 16384;

        // --- S = Q K^T ---
        float S[8][4];
        #pragma unroll
        for (int i = 0; i < 8; i++)
            #pragma unroll
            for (int r = 0; r < 4; r++) S[i][r] = 0.f;

        #pragma unroll
        for (int ks = 0; ks < 4; ks++) {
            uint32_t ah[4], al[4];
            ldmx4(ah, aQh + sw128(rowQ, ks * 32 + colB));
            ldmx4(al, aQl + sw128(rowQ, ks * 32 + colB));
            #pragma unroll
            for (int g = 0; g < 4; g++) {
                uint32_t kh[4], kl[4];
                int r = g * 16 + kRow;
                ldmx4(kh, aKh + sw128(r, ks * 32 + colB));
                ldmx4(kl, aKl + sw128(r, ks * 32 + colB));
                uint32_t be[2]  = {kh[0], kh[2]};
                uint32_t bo[2]  = {kh[1], kh[3]};
                uint32_t bel[2] = {kl[0], kl[2]};
                uint32_t bol[2] = {kl[1], kl[3]};
                mma_bf(S[2*g],   ah, be);
                mma_bf(S[2*g],   ah, bel);
                mma_bf(S[2*g],   al, be);
                mma_bf(S[2*g+1], ah, bo);
                mma_bf(S[2*g+1], ah, bol);
                mma_bf(S[2*g+1], al, bo);
            }
        }

        // --- causal mask ---
        if (kv0 + 63 > rowbase) {
            int r0 = rowbase + (lane >> 2);
            #pragma unroll
            for (int nf = 0; nf < 8; nf++) {
                int c0 = kv0 + nf * 8 + (lane & 3) * 2;
                if (c0 > r0)          S[nf][0] = -1e5f;
                if (c0 + 1 > r0)      S[nf][1] = -1e5f;
                if (c0 > r0 + 8)      S[nf][2] = -1e5f;
                if (c0 + 1 > r0 + 8)  S[nf][3] = -1e5f;
            }
        }

        // --- P = exp(S) (fp16 A-frag layout) + row sums ---
        uint32_t P[8][2];
        #pragma unroll
        for (int nf = 0; nf < 8; nf++) {
            __half2 h0 = __floats2half2_rn(S[nf][0] * csc, S[nf][1] * csc);
            __half2 h1 = __floats2half2_rn(S[nf][2] * csc, S[nf][3] * csc);
            uint32_t p0 = ex2_f16x2(*(uint32_t*)&h0);
            uint32_t p1 = ex2_f16x2(*(uint32_t*)&h1);
            P[nf][0] = p0;
            P[nf][1] = p1;
            float2 f0 = __half22float2(*(__half2*)&p0);
            float2 f1 = __half22float2(*(__half2*)&p1);
            lr  += f0.x + f0.y;
            lr8 += f1.x + f1.y;
        }

        // --- O += P @ V ---
        #pragma unroll
        for (int j = 0; j < 4; j++) {
            uint32_t a[4] = { P[2*j][0], P[2*j][1], P[2*j+1][0], P[2*j+1][1] };
            int r = j * 16 + vRow;
            #pragma unroll
            for (int dg = 0; dg < 2; dg++) {
                uint32_t vv[4], vv2[4];
                ldmx4t(vv,  aV + sw128(r, dg * 64 + colB));
                ldmx4t(vv2, aV + sw128(r, dg * 64 + 32 + colB));
                mma_hf(accO[4*dg + 0], a, &vv[0]);
                mma_hf(accO[4*dg + 1], a, &vv[2]);
                mma_hf(accO[4*dg + 2], a, &vv2[0]);
                mma_hf(accO[4*dg + 3], a, &vv2[2]);
            }
        }
    }

    lr  += __shfl_xor_sync(0xffffffffu, lr, 1);
    lr  += __shfl_xor_sync(0xffffffffu, lr, 2);
    lr8 += __shfl_xor_sync(0xffffffffu, lr8, 1);
    lr8 += __shfl_xor_sync(0xffffffffu, lr8, 2);
    const float inv  = 1.f / lr;
    const float inv8 = 1.f / lr8;

    const int grow = b * TSEQ + q0 + wid * 16 + (lane >> 2);
    #pragma unroll
    for (int dg = 0; dg < 8; dg++) {
        int col = cbase + dg * 8 + (lane & 3) * 2;
        uint32_t hi, lo;
        bfsplit2(accO[dg][0] * inv, accO[dg][1] * inv, hi, lo);
        size_t i0 = (size_t)grow * DMODEL + col;
        *(uint32_t*)&oh[i0] = hi;
        *(uint32_t*)&ol[i0] = lo;
        bfsplit2(accO[dg][2] * inv8, accO[dg][3] * inv8, hi, lo);
        size_t i1 = (size_t)(grow + 8) * DMODEL + col;
        *(uint32_t*)&oh[i1] = hi;
        *(uint32_t*)&ol[i1] = lo;
    }
}

// ---------------------------------------------------------------------------
extern "C" void kernel_launch(void* const* d_in, const int* in_sizes, int n_in,
                              void* d_out, int out_size)
{
    const float* x     = (const float*)d_in[0];
    const float* W_qkv = (const float*)d_in[1];
    const float* W_out = (const float*)d_in[2];
    float* out = (float*)d_out;

    __nv_bfloat16 *xh, *xl, *wqh, *wql, *woh, *wol, *ah, *al;
    __nv_bfloat16 *Qh, *Ql, *Kh, *Kl;
    __half *Vh;
    cudaGetSymbolAddress((void**)&xh,  g_xh);
    cudaGetSymbolAddress((void**)&xl,  g_xl);
    cudaGetSymbolAddress((void**)&wqh, g_wqh);
    cudaGetSymbolAddress((void**)&wql, g_wql);
    cudaGetSymbolAddress((void**)&woh, g_woh);
    cudaGetSymbolAddress((void**)&wol, g_wol);
    cudaGetSymbolAddress((void**)&ah,  g_ah);
    cudaGetSymbolAddress((void**)&al,  g_al);
    cudaGetSymbolAddress((void**)&Qh,  g_Qh);
    cudaGetSymbolAddress((void**)&Ql,  g_Ql);
    cudaGetSymbolAddress((void**)&Kh,  g_Kh);
    cudaGetSymbolAddress((void**)&Kl,  g_Kl);
    cudaGetSymbolAddress((void**)&Vh,  g_Vh);

    cudaFuncSetAttribute(tc_gemm4<0>, cudaFuncAttributeMaxDynamicSharedMemorySize,
                         GEMM_SMEM);
    cudaFuncSetAttribute(tc_gemm4<1>, cudaFuncAttributeMaxDynamicSharedMemorySize,
                         GEMM_SMEM);
    cudaFuncSetAttribute(flash_attn_tc4, cudaFuncAttributeMaxDynamicSharedMemorySize,
                         ATTN_SMEM);

    // 0) Split inputs
    {
        int n4 = MTOK * DMODEL / 4;
        split_bf16<<<(n4 + 255) / 256, 256>>>(x, xh, xl, n4);
        int w4 = DMODEL * QKV_N / 4;
        split_bf16<<<(w4 + 255) / 256, 256>>>(W_qkv, wqh, wql, w4);
        int o4 = DMODEL * DMODEL / 4;
        split_bf16<<<(o4 + 255) / 256, 256>>>(W_out, woh, wol, o4);
    }

    // 1) QKV projection -> split Q/K (bf16 hi/lo) + V (fp16), [tok][1024]
    tc_gemm4<0><<<dim3(QKV_N / 128, MTOK / 128), 256, GEMM_SMEM>>>(
        xh, xl, wqh, wql, nullptr, MTOK, QKV_N, DMODEL);

    // 2) Causal flash attention -> bf16 hi/lo output
    flash_attn_tc4<<<dim3(TSEQ / 128, BATCH * NHEADS), 256, ATTN_SMEM>>>(
        Qh, Ql, Kh, Kl, Vh, ah, al);

    // 3) Output projection (fp32 out)
    tc_gemm4<1><<<dim3(DMODEL / 128, MTOK / 128), 256, GEMM_SMEM>>>(
        ah, al, woh, wol, out, MTOK, DMODEL, DMODEL);
}

// round 10
// speedup vs baseline: 1.5392x; 1.5392x over previous
#include <cuda_runtime.h>
#include <cuda_bf16.h>
#include <cuda_fp16.h>
#include <math.h>
#include <stdint.h>

// Problem constants
#define BATCH   4
#define TSEQ    2048
#define DMODEL  1024
#define NHEADS  16
#define DHEAD   64
#define MTOK    (BATCH * TSEQ)       // 8192 rows
#define QKV_N   (3 * DMODEL)         // 3072

// Scratch (no cudaMalloc). Per-token layouts are [tok][1024] (h*64+d).
__device__ __nv_bfloat16 g_Qh[(size_t)MTOK * DMODEL];
__device__ __nv_bfloat16 g_Ql[(size_t)MTOK * DMODEL];
__device__ __nv_bfloat16 g_Kh[(size_t)MTOK * DMODEL];
__device__ __nv_bfloat16 g_Kl[(size_t)MTOK * DMODEL];
__device__ __half        g_Vh[(size_t)MTOK * DMODEL];
__device__ __nv_bfloat16 g_xh[(size_t)MTOK * DMODEL];
__device__ __nv_bfloat16 g_xl[(size_t)MTOK * DMODEL];
__device__ __nv_bfloat16 g_wqh[(size_t)DMODEL * QKV_N];
__device__ __nv_bfloat16 g_wql[(size_t)DMODEL * QKV_N];
__device__ __half        g_wo16[(size_t)DMODEL * DMODEL];   // W_out fp16
__device__ __half        g_ah[(size_t)MTOK * DMODEL];       // attn out fp16 hi
__device__ __half        g_al[(size_t)MTOK * DMODEL];       // attn out fp16 lo

// ---------------------------------------------------------------------------
// PTX helpers
// ---------------------------------------------------------------------------
__device__ __forceinline__ uint32_t smem_u32(const void* p) {
    uint32_t a;
    asm("{ .reg .u64 t; cvta.to.shared.u64 t, %1; cvt.u32.u64 %0, t; }"
        : "=r"(a) : "l"(p));
    return a;
}
__device__ __forceinline__ void ldmx4(uint32_t* r, uint32_t addr) {
    asm volatile("ldmatrix.sync.aligned.m8n8.x4.shared.b16 {%0,%1,%2,%3}, [%4];"
                 : "=r"(r[0]), "=r"(r[1]), "=r"(r[2]), "=r"(r[3]) : "r"(addr));
}
__device__ __forceinline__ void ldmx4t(uint32_t* r, uint32_t addr) {
    asm volatile("ldmatrix.sync.aligned.m8n8.x4.trans.shared.b16 {%0,%1,%2,%3}, [%4];"
                 : "=r"(r[0]), "=r"(r[1]), "=r"(r[2]), "=r"(r[3]) : "r"(addr));
}
__device__ __forceinline__ void mma_bf(float* c, const uint32_t* a, const uint32_t* b) {
    asm volatile(
        "mma.sync.aligned.m16n8k16.row.col.f32.bf16.bf16.f32 "
        "{%0,%1,%2,%3}, {%4,%5,%6,%7}, {%8,%9}, {%0,%1,%2,%3};"
        : "+f"(c[0]), "+f"(c[1]), "+f"(c[2]), "+f"(c[3])
        : "r"(a[0]), "r"(a[1]), "r"(a[2]), "r"(a[3]), "r"(b[0]), "r"(b[1]));
}
__device__ __forceinline__ void mma_hf(float* c, const uint32_t* a, const uint32_t* b) {
    asm volatile(
        "mma.sync.aligned.m16n8k16.row.col.f32.f16.f16.f32 "
        "{%0,%1,%2,%3}, {%4,%5,%6,%7}, {%8,%9}, {%0,%1,%2,%3};"
        : "+f"(c[0]), "+f"(c[1]), "+f"(c[2]), "+f"(c[3])
        : "r"(a[0]), "r"(a[1]), "r"(a[2]), "r"(a[3]), "r"(b[0]), "r"(b[1]));
}
__device__ __forceinline__ uint32_t ex2_f16x2(uint32_t x) {
    uint32_t r;
    asm("ex2.approx.f16x2 %0, %1;" : "=r"(r) : "r"(x));
    return r;
}
__device__ __forceinline__ void cpa16(uint32_t dst, const void* src) {
    asm volatile("cp.async.cg.shared.global [%0], [%1], 16;" :: "r"(dst), "l"(src));
}
// SW128 swizzle for 128-byte-pitch rows (attention smem only)
__device__ __forceinline__ uint32_t sw128(int row, int byteoff) {
    return (uint32_t)(row * 128 + (byteoff ^ ((row & 7) << 4)));
}
__device__ __forceinline__ void bfsplit2(float a, float b, uint32_t& hi, uint32_t& lo) {
    __nv_bfloat162 h, l;
    h.x = __float2bfloat16_rn(a);
    h.y = __float2bfloat16_rn(b);
    l.x = __float2bfloat16_rn(a - __bfloat162float(h.x));
    l.y = __float2bfloat16_rn(b - __bfloat162float(h.y));
    hi = *(uint32_t*)&h;
    lo = *(uint32_t*)&l;
}
__device__ __forceinline__ void hfsplit2(float a, float b, uint32_t& hi, uint32_t& lo) {
    __half2 h, l;
    h.x = __float2half_rn(a);
    h.y = __float2half_rn(b);
    l.x = __float2half_rn(a - __half2float(h.x));
    l.y = __float2half_rn(b - __half2float(h.y));
    hi = *(uint32_t*)&h;
    lo = *(uint32_t*)&l;
}

// ---------------------------------------------------------------------------
// fp32 -> bf16 hi/lo split ; fp32 -> fp16 convert
// ---------------------------------------------------------------------------
__global__ __launch_bounds__(256) void split_bf16(
    const float* __restrict__ in, __nv_bfloat16* __restrict__ hi,
    __nv_bfloat16* __restrict__ lo, int n4)
{
    int i = blockIdx.x * blockDim.x + threadIdx.x;
    if (i >= n4) return;
    float4 v = ((const float4*)in)[i];
    uint32_t h0, l0, h1, l1;
    bfsplit2(v.x, v.y, h0, l0);
    bfsplit2(v.z, v.w, h1, l1);
    ((uint2*)hi)[i] = make_uint2(h0, h1);
    ((uint2*)lo)[i] = make_uint2(l0, l1);
}
__global__ __launch_bounds__(256) void conv_f16(
    const float* __restrict__ in, __half* __restrict__ o16, int n4)
{
    int i = blockIdx.x * blockDim.x + threadIdx.x;
    if (i >= n4) return;
    float4 v = ((const float4*)in)[i];
    __half2 a = __floats2half2_rn(v.x, v.y);
    __half2 b = __floats2half2_rn(v.z, v.w);
    ((uint2*)o16)[i] = make_uint2(*(uint32_t*)&a, *(uint32_t*)&b);
}

// ---------------------------------------------------------------------------
// QKV GEMM: bf16 hi/lo 3-term, R7-proven schedule
//   { prefetch(c+1); wait_group 1; sync; mma(c); sync }
// Epilogue scatter-splits into g_Qh/Ql/Kh/Kl (bf16) + g_Vh (fp16), [tok][1024].
// ---------------------------------------------------------------------------
#define GPAD_A 40
#define GPAD_B 136
#define STAGE_A (128 * GPAD_A)
#define STAGE_B (32 * GPAD_B)
#define STAGE_ELEMS (2 * STAGE_A + 2 * STAGE_B)
#define GEMM_SMEM (2 * STAGE_ELEMS * 2)

__global__ __launch_bounds__(256, 2) void tc_gemm_qkv(
    const __nv_bfloat16* __restrict__ Ah, const __nv_bfloat16* __restrict__ Al,
    const __nv_bfloat16* __restrict__ Bh, const __nv_bfloat16* __restrict__ Bl,
    int M, int N, int K)
{
    extern __shared__ __nv_bfloat16 sm[];
    const uint32_t smb = smem_u32(sm);

    const int tid  = threadIdx.x;
    const int lane = tid & 31;
    const int wid  = tid >> 5;
    const int wm   = wid & 1;
    const int wn   = wid >> 1;
    const int crow = blockIdx.y * 128;
    const int ccol = blockIdx.x * 128;

    const int arow0 = tid >> 2;
    const int ach   = (tid & 3) * 8;
    const int brow0 = tid >> 4;
    const int bch   = (tid & 15) * 8;

    auto prefetch = [&](int c) {
        const uint32_t sb = smb + (uint32_t)(c & 1) * (STAGE_ELEMS * 2);
        const size_t ka = (size_t)c * 32;
        #pragma unroll
        for (int j = 0; j < 2; j++) {
            int row = arow0 + j * 64;
            const __nv_bfloat16* sh = Ah + (size_t)(crow + row) * K + ka + ach;
            const __nv_bfloat16* sl = Al + (size_t)(crow + row) * K + ka + ach;
            uint32_t d = sb + (uint32_t)(row * GPAD_A + ach) * 2;
            cpa16(d, sh);
            cpa16(d + STAGE_A * 2, sl);
        }
        #pragma unroll
        for (int j = 0; j < 2; j++) {
            int row = brow0 + j * 16;
            const __nv_bfloat16* sh = Bh + (ka + row) * N + ccol + bch;
            const __nv_bfloat16* sl = Bl + (ka + row) * N + ccol + bch;
            uint32_t d = sb + (uint32_t)(2 * STAGE_A + row * GPAD_B + bch) * 2;
            cpa16(d, sh);
            cpa16(d + STAGE_B * 2, sl);
        }
        asm volatile("cp.async.commit_group;" ::: "memory");
    };

    const int aRowBase = wm * 64 + (lane & 15);
    const int aColOff  = (lane >> 4) * 8;
    const int bKrow    = (lane & 7) + ((lane >> 3) & 1) * 8;
    const int bNBase   = wn * 32 + (lane >> 4) * 8;

    float acc[4][4][4];
    #pragma unroll
    for (int i = 0; i < 4; i++)
        #pragma unroll
        for (int j = 0; j < 4; j++)
            #pragma unroll
            for (int r = 0; r < 4; r++) acc[i][j][r] = 0.f;

    const int nchunks = K >> 5;
    prefetch(0);

    for (int c = 0; c < nchunks; c++) {
        if (c + 1 < nchunks) {
            prefetch(c + 1);
            asm volatile("cp.async.wait_group 1;" ::: "memory");
        } else {
            asm volatile("cp.async.wait_group 0;" ::: "memory");
        }
        __syncthreads();

        const uint32_t sb  = smb + (uint32_t)(c & 1) * (STAGE_ELEMS * 2);
        const uint32_t bAh = sb;
        const uint32_t bAl = sb + STAGE_A * 2;
        const uint32_t bBh = sb + 2 * STAGE_A * 2;
        const uint32_t bBl = bBh + STAGE_B * 2;

        #pragma unroll
        for (int ks = 0; ks < 2; ks++) {
            uint32_t ah[4][4], al[4][4], bh[2][4], bl[2][4];
            #pragma unroll
            for (int mf = 0; mf < 4; mf++) {
                uint32_t off = (uint32_t)((aRowBase + mf * 16) * GPAD_A + ks * 16 + aColOff) * 2;
                ldmx4(ah[mf], bAh + off);
                ldmx4(al[mf], bAl + off);
            }
            #pragma unroll
            for (int nf2 = 0; nf2 < 2; nf2++) {
                uint32_t off = (uint32_t)((ks * 16 + bKrow) * GPAD_B + bNBase + nf2 * 16) * 2;
                ldmx4t(bh[nf2], bBh + off);
                ldmx4t(bl[nf2], bBl + off);
            }
            #pragma unroll
            for (int mf = 0; mf < 4; mf++)
                #pragma unroll
                for (int nf = 0; nf < 4; nf++) {
                    const uint32_t* bhp = &bh[nf >> 1][(nf & 1) * 2];
                    const uint32_t* blp = &bl[nf >> 1][(nf & 1) * 2];
                    mma_bf(acc[mf][nf], ah[mf], bhp);
                    mma_bf(acc[mf][nf], ah[mf], blp);
                    mma_bf(acc[mf][nf], al[mf], bhp);
                }
        }
        __syncthreads();
    }

    // qkv split epilogue: n -> sect (q/k/v) + col (h*64+d), [tok][1024]
    const int nbase = ccol + wn * 32;
    const int sect  = nbase >> 10;
    #pragma unroll
    for (int mf = 0; mf < 4; mf++) {
        int m0 = crow + wm * 64 + mf * 16 + (lane >> 2);
        #pragma unroll
        for (int nf = 0; nf < 4; nf++) {
            int col = (nbase + nf * 8 + (lane & 3) * 2) & 1023;
            #pragma unroll
            for (int r2 = 0; r2 < 2; r2++) {
                size_t di = (size_t)(m0 + r2 * 8) * 1024 + col;
                float o0 = acc[mf][nf][r2 * 2], o1 = acc[mf][nf][r2 * 2 + 1];
                if (sect == 2) {
                    __half2 hv = __floats2half2_rn(o0, o1);
                    *(__half2*)&g_Vh[di] = hv;
                } else {
                    uint32_t hi, lo;
                    bfsplit2(o0, o1, hi, lo);
                    if (sect == 0) {
                        *(uint32_t*)&g_Qh[di] = hi;
                        *(uint32_t*)&g_Ql[di] = lo;
                    } else {
                        *(uint32_t*)&g_Kh[di] = hi;
                        *(uint32_t*)&g_Kl[di] = lo;
                    }
                }
            }
        }
    }
}

// ---------------------------------------------------------------------------
// Output GEMM: fp16 hi/lo 2-term (A = attn out fp16 hi/lo, B = W_out fp16).
// Same R7 schedule; smaller stage (no B-lo). fp32 epilogue.
// ---------------------------------------------------------------------------
#define OSTAGE_BYTES (2 * STAGE_A * 2 + STAGE_B * 2)   // Ah,Al + Bh = 29184
#define OGEMM_SMEM (2 * OSTAGE_BYTES)

__global__ __launch_bounds__(256, 2) void tc_gemm_out(
    const __half* __restrict__ Ah, const __half* __restrict__ Al,
    const __half* __restrict__ Bh,
    float* __restrict__ C, int M, int N, int K)
{
    extern __shared__ __half smo[];
    const uint32_t smb = smem_u32(smo);

    const int tid  = threadIdx.x;
    const int lane = tid & 31;
    const int wid  = tid >> 5;
    const int wm   = wid & 1;
    const int wn   = wid >> 1;
    const int crow = blockIdx.y * 128;
    const int ccol = blockIdx.x * 128;

    const int arow0 = tid >> 2;
    const int ach   = (tid & 3) * 8;
    const int brow0 = tid >> 4;
    const int bch   = (tid & 15) * 8;

    auto prefetch = [&](int c) {
        const uint32_t sb = smb + (uint32_t)(c & 1) * OSTAGE_BYTES;
        const size_t ka = (size_t)c * 32;
        #pragma unroll
        for (int j = 0; j < 2; j++) {
            int row = arow0 + j * 64;
            const __half* sh = Ah + (size_t)(crow + row) * K + ka + ach;
            const __half* sl = Al + (size_t)(crow + row) * K + ka + ach;
            uint32_t d = sb + (uint32_t)(row * GPAD_A + ach) * 2;
            cpa16(d, sh);
            cpa16(d + STAGE_A * 2, sl);
        }
        #pragma unroll
        for (int j = 0; j < 2; j++) {
            int row = brow0 + j * 16;
            cpa16(sb + (uint32_t)(2 * STAGE_A + row * GPAD_B + bch) * 2,
                  Bh + (size_t)(ka + row) * N + ccol + bch);
        }
        asm volatile("cp.async.commit_group;" ::: "memory");
    };

    const int aRowBase = wm * 64 + (lane & 15);
    const int aColOff  = (lane >> 4) * 8;
    const int bKrow    = (lane & 7) + ((lane >> 3) & 1) * 8;
    const int bNBase   = wn * 32 + (lane >> 4) * 8;

    float acc[4][4][4];
    #pragma unroll
    for (int i = 0; i < 4; i++)
        #pragma unroll
        for (int j = 0; j < 4; j++)
            #pragma unroll
            for (int r = 0; r < 4; r++) acc[i][j][r] = 0.f;

    const int nchunks = K >> 5;
    prefetch(0);

    for (int c = 0; c < nchunks; c++) {
        if (c + 1 < nchunks) {
            prefetch(c + 1);
            asm volatile("cp.async.wait_group 1;" ::: "memory");
        } else {
            asm volatile("cp.async.wait_group 0;" ::: "memory");
        }
        __syncthreads();

        const uint32_t sb  = smb + (uint32_t)(c & 1) * OSTAGE_BYTES;
        const uint32_t bAh = sb;
        const uint32_t bAl = sb + STAGE_A * 2;
        const uint32_t bBh = sb + 2 * STAGE_A * 2;

        #pragma unroll
        for (int ks = 0; ks < 2; ks++) {
            uint32_t ah[4][4], al[4][4], bh[2][4];
            #pragma unroll
            for (int mf = 0; mf < 4; mf++) {
                uint32_t off = (uint32_t)((aRowBase + mf * 16) * GPAD_A + ks * 16 + aColOff) * 2;
                ldmx4(ah[mf], bAh + off);
                ldmx4(al[mf], bAl + off);
            }
            #pragma unroll
            for (int nf2 = 0; nf2 < 2; nf2++) {
                uint32_t off = (uint32_t)((ks * 16 + bKrow) * GPAD_B + bNBase + nf2 * 16) * 2;
                ldmx4t(bh[nf2], bBh + off);
            }
            #pragma unroll
            for (int mf = 0; mf < 4; mf++)
                #pragma unroll
                for (int nf = 0; nf < 4; nf++) {
                    const uint32_t* bhp = &bh[nf >> 1][(nf & 1) * 2];
                    mma_hf(acc[mf][nf], ah[mf], bhp);
                    mma_hf(acc[mf][nf], al[mf], bhp);
                }
        }
        __syncthreads();
    }

    #pragma unroll
    for (int mf = 0; mf < 4; mf++) {
        int row0 = crow + wm * 64 + mf * 16 + (lane >> 2);
        #pragma unroll
        for (int nf = 0; nf < 4; nf++) {
            int col = ccol + wn * 32 + nf * 8 + (lane & 3) * 2;
            *(float2*)&C[(size_t)row0 * N + col] =
                make_float2(acc[mf][nf][0], acc[mf][nf][1]);
            *(float2*)&C[(size_t)(row0 + 8) * N + col] =
                make_float2(acc[mf][nf][2], acc[mf][nf][3]);
        }
    }
}

// ---------------------------------------------------------------------------
// Tensor-core causal flash attention (R7-proven core; fp16 hi/lo output).
// smem: Qh 16K | Ql 16K | Kh 8K | Kl 8K | V 8K = 56 KB, SW128 128B rows.
// ---------------------------------------------------------------------------
#define ATTN_SMEM (16384 * 2 + 8192 * 3)

__global__ __launch_bounds__(256, 2) void flash_attn_tc5(
    const __nv_bfloat16* __restrict__ Qh, const __nv_bfloat16* __restrict__ Ql,
    const __nv_bfloat16* __restrict__ Kh, const __nv_bfloat16* __restrict__ Kl,
    const __half* __restrict__ Vh,
    __half* __restrict__ oh, __half* __restrict__ ol)
{
    extern __shared__ char smraw[];
    char* pQh = smraw;
    char* pQl = smraw + 16384;
    char* pKh = smraw + 32768;
    char* pKl = pKh + 8192;
    char* pV  = pKl + 8192;

    const int tid = threadIdx.x, lane = tid & 31, wid = tid >> 5;
    const int b  = blockIdx.y >> 4;
    const int h  = blockIdx.y & 15;
    const int qt = gridDim.x - 1 - blockIdx.x;   // heavy tiles first
    const int q0 = qt * 128;

    const size_t rbase = (size_t)b * 2048;
    const int    cbase = h * 64;

    #pragma unroll
    for (int i = 0; i < 4; i++) {
        int li = i * 256 + tid;
        int r = li >> 3, ch = li & 7;
        size_t gi = (rbase + q0 + r) * 1024 + cbase + ch * 8;
        uint32_t so = sw128(r, ch * 16);
        *(uint4*)(pQh + so) = *(const uint4*)(Qh + gi);
        *(uint4*)(pQl + so) = *(const uint4*)(Ql + gi);
    }

    const uint32_t aQh = smem_u32(pQh), aQl = smem_u32(pQl);
    const uint32_t aKh = smem_u32(pKh), aKl = smem_u32(pKl);
    const uint32_t aV  = smem_u32(pV);

    const int rowQ = wid * 16 + (lane & 15);
    const int colB = (lane >> 4) * 16;              // bytes
    const int kRow = lane & 15;
    const int vRow = (lane & 7) + ((lane >> 3) & 1) * 8;

    float accO[8][4];
    #pragma unroll
    for (int i = 0; i < 8; i++)
        #pragma unroll
        for (int r = 0; r < 4; r++) accO[i][r] = 0.f;
    float lr = 0.f, lr8 = 0.f;

    const int rowbase = q0 + wid * 16;
    const int nkt = 2 * qt + 2;
    const float csc = 0.1803368802f;   // log2(e)/8

    for (int kt = 0; kt < nkt; kt++) {
        const int kv0 = kt * 64;
        __syncthreads();

        #pragma unroll
        for (int i = 0; i < 2; i++) {
            int li = i * 256 + tid;
            int r = li >> 3, ch = li & 7;
            size_t gi = (rbase + kv0 + r) * 1024 + cbase + ch * 8;
            uint32_t so = sw128(r, ch * 16);
            *(uint4*)(pKh + so) = *(const uint4*)(Kh + gi);
            *(uint4*)(pKl + so) = *(const uint4*)(Kl + gi);
            *(uint4*)(pV  + so) = *(const uint4*)(Vh + gi);
        }
        __syncthreads();

        // --- S = Q K^T ---
        float S[8][4];
        #pragma unroll
        for (int i = 0; i < 8; i++)
            #pragma unroll
            for (int r = 0; r < 4; r++) S[i][r] = 0.f;

        #pragma unroll
        for (int ks = 0; ks < 4; ks++) {
            uint32_t ah[4], al[4];
            ldmx4(ah, aQh + sw128(rowQ, ks * 32 + colB));
            ldmx4(al, aQl + sw128(rowQ, ks * 32 + colB));
            #pragma unroll
            for (int g = 0; g < 4; g++) {
                uint32_t kh[4], kl[4];
                int r = g * 16 + kRow;
                ldmx4(kh, aKh + sw128(r, ks * 32 + colB));
                ldmx4(kl, aKl + sw128(r, ks * 32 + colB));
                uint32_t be[2]  = {kh[0], kh[2]};
                uint32_t bo[2]  = {kh[1], kh[3]};
                uint32_t bel[2] = {kl[0], kl[2]};
                uint32_t bol[2] = {kl[1], kl[3]};
                mma_bf(S[2*g],   ah, be);
                mma_bf(S[2*g],   ah, bel);
                mma_bf(S[2*g],   al, be);
                mma_bf(S[2*g+1], ah, bo);
                mma_bf(S[2*g+1], ah, bol);
                mma_bf(S[2*g+1], al, bo);
            }
        }

        // --- causal mask ---
        if (kv0 + 63 > rowbase) {
            int r0 = rowbase + (lane >> 2);
            #pragma unroll
            for (int nf = 0; nf < 8; nf++) {
                int c0 = kv0 + nf * 8 + (lane & 3) * 2;
                if (c0 > r0)          S[nf][0] = -1e5f;
                if (c0 + 1 > r0)      S[nf][1] = -1e5f;
                if (c0 > r0 + 8)      S[nf][2] = -1e5f;
                if (c0 + 1 > r0 + 8)  S[nf][3] = -1e5f;
            }
        }

        // --- P = exp(S) (fp16 A-frag layout) + row sums ---
        uint32_t P[8][2];
        #pragma unroll
        for (int nf = 0; nf < 8; nf++) {
            __half2 h0 = __floats2half2_rn(S[nf][0] * csc, S[nf][1] * csc);
            __half2 h1 = __floats2half2_rn(S[nf][2] * csc, S[nf][3] * csc);
            uint32_t p0 = ex2_f16x2(*(uint32_t*)&h0);
            uint32_t p1 = ex2_f16x2(*(uint32_t*)&h1);
            P[nf][0] = p0;
            P[nf][1] = p1;
            float2 f0 = __half22float2(*(__half2*)&p0);
            float2 f1 = __half22float2(*(__half2*)&p1);
            lr  += f0.x + f0.y;
            lr8 += f1.x + f1.y;
        }

        // --- O += P @ V ---
        #pragma unroll
        for (int j = 0; j < 4; j++) {
            uint32_t a[4] = { P[2*j][0], P[2*j][1], P[2*j+1][0], P[2*j+1][1] };
            int r = j * 16 + vRow;
            #pragma unroll
            for (int dg = 0; dg < 2; dg++) {
                uint32_t vv[4], vv2[4];
                ldmx4t(vv,  aV + sw128(r, dg * 64 + colB));
                ldmx4t(vv2, aV + sw128(r, dg * 64 + 32 + colB));
                mma_hf(accO[4*dg + 0], a, &vv[0]);
                mma_hf(accO[4*dg + 1], a, &vv[2]);
                mma_hf(accO[4*dg + 2], a, &vv2[0]);
                mma_hf(accO[4*dg + 3], a, &vv2[2]);
            }
        }
    }

    lr  += __shfl_xor_sync(0xffffffffu, lr, 1);
    lr  += __shfl_xor_sync(0xffffffffu, lr, 2);
    lr8 += __shfl_xor_sync(0xffffffffu, lr8, 1);
    lr8 += __shfl_xor_sync(0xffffffffu, lr8, 2);
    const float inv  = 1.f / lr;
    const float inv8 = 1.f / lr8;

    const int grow = b * TSEQ + q0 + wid * 16 + (lane >> 2);
    #pragma unroll
    for (int dg = 0; dg < 8; dg++) {
        int col = cbase + dg * 8 + (lane & 3) * 2;
        uint32_t hi, lo;
        hfsplit2(accO[dg][0] * inv, accO[dg][1] * inv, hi, lo);
        size_t i0 = (size_t)grow * DMODEL + col;
        *(uint32_t*)&oh[i0] = hi;
        *(uint32_t*)&ol[i0] = lo;
        hfsplit2(accO[dg][2] * inv8, accO[dg][3] * inv8, hi, lo);
        size_t i1 = (size_t)(grow + 8) * DMODEL + col;
        *(uint32_t*)&oh[i1] = hi;
        *(uint32_t*)&ol[i1] = lo;
    }
}

// ---------------------------------------------------------------------------
extern "C" void kernel_launch(void* const* d_in, const int* in_sizes, int n_in,
                              void* d_out, int out_size)
{
    const float* x     = (const float*)d_in[0];
    const float* W_qkv = (const float*)d_in[1];
    const float* W_out = (const float*)d_in[2];
    float* out = (float*)d_out;

    __nv_bfloat16 *xh, *xl, *wqh, *wql, *Qh, *Ql, *Kh, *Kl;
    __half *Vh, *wo16, *ah, *al;
    cudaGetSymbolAddress((void**)&xh,   g_xh);
    cudaGetSymbolAddress((void**)&xl,   g_xl);
    cudaGetSymbolAddress((void**)&wqh,  g_wqh);
    cudaGetSymbolAddress((void**)&wql,  g_wql);
    cudaGetSymbolAddress((void**)&wo16, g_wo16);
    cudaGetSymbolAddress((void**)&ah,   g_ah);
    cudaGetSymbolAddress((void**)&al,   g_al);
    cudaGetSymbolAddress((void**)&Qh,   g_Qh);
    cudaGetSymbolAddress((void**)&Ql,   g_Ql);
    cudaGetSymbolAddress((void**)&Kh,   g_Kh);
    cudaGetSymbolAddress((void**)&Kl,   g_Kl);
    cudaGetSymbolAddress((void**)&Vh,   g_Vh);

    cudaFuncSetAttribute(tc_gemm_qkv, cudaFuncAttributeMaxDynamicSharedMemorySize,
                         GEMM_SMEM);
    cudaFuncSetAttribute(tc_gemm_out, cudaFuncAttributeMaxDynamicSharedMemorySize,
                         OGEMM_SMEM);
    cudaFuncSetAttribute(flash_attn_tc5, cudaFuncAttributeMaxDynamicSharedMemorySize,
                         ATTN_SMEM);

    // 0) Split / convert inputs
    {
        int n4 = MTOK * DMODEL / 4;
        split_bf16<<<(n4 + 255) / 256, 256>>>(x, xh, xl, n4);
        int w4 = DMODEL * QKV_N / 4;
        split_bf16<<<(w4 + 255) / 256, 256>>>(W_qkv, wqh, wql, w4);
        int o4 = DMODEL * DMODEL / 4;
        conv_f16<<<(o4 + 255) / 256, 256>>>(W_out, wo16, o4);
    }

    // 1) QKV projection -> split Q/K (bf16 hi/lo) + V (fp16), [tok][1024]
    tc_gemm_qkv<<<dim3(QKV_N / 128, MTOK / 128), 256, GEMM_SMEM>>>(
        xh, xl, wqh, wql, MTOK, QKV_N, DMODEL);

    // 2) Causal flash attention -> fp16 hi/lo output
    flash_attn_tc5<<<dim3(TSEQ / 128, BATCH * NHEADS), 256, ATTN_SMEM>>>(
        Qh, Ql, Kh, Kl, Vh, ah, al);

    // 3) Output projection: fp16 2-term (fp32 out)
    tc_gemm_out<<<dim3(DMODEL / 128, MTOK / 128), 256, OGEMM_SMEM>>>(
        ah, al, wo16, out, MTOK, DMODEL, DMODEL);
}

// round 11
// speedup vs baseline: 2.0782x; 1.3502x over previous
#include <cuda_runtime.h>
#include <cuda_bf16.h>
#include <cuda_fp16.h>
#include <math.h>
#include <stdint.h>

// Problem constants
#define BATCH   4
#define TSEQ    2048
#define DMODEL  1024
#define NHEADS  16
#define DHEAD   64
#define MTOK    (BATCH * TSEQ)       // 8192 rows
#define QKV_N   (3 * DMODEL)         // 3072

// Scratch (no cudaMalloc). Per-token layouts are [tok][1024] (h*64+d).
__device__ __half g_Q16[(size_t)MTOK * DMODEL];
__device__ __half g_K16[(size_t)MTOK * DMODEL];
__device__ __half g_V16[(size_t)MTOK * DMODEL];
__device__ __half g_x16h[(size_t)MTOK * DMODEL];
__device__ __half g_x16l[(size_t)MTOK * DMODEL];
__device__ __half g_wq16[(size_t)DMODEL * QKV_N];
__device__ __half g_wo16[(size_t)DMODEL * DMODEL];
__device__ __half g_ah[(size_t)MTOK * DMODEL];       // attn out fp16 hi
__device__ __half g_al[(size_t)MTOK * DMODEL];       // attn out fp16 lo

// ---------------------------------------------------------------------------
// PTX helpers
// ---------------------------------------------------------------------------
__device__ __forceinline__ uint32_t smem_u32(const void* p) {
    uint32_t a;
    asm("{ .reg .u64 t; cvta.to.shared.u64 t, %1; cvt.u32.u64 %0, t; }"
        : "=r"(a) : "l"(p));
    return a;
}
__device__ __forceinline__ void ldmx4(uint32_t* r, uint32_t addr) {
    asm volatile("ldmatrix.sync.aligned.m8n8.x4.shared.b16 {%0,%1,%2,%3}, [%4];"
                 : "=r"(r[0]), "=r"(r[1]), "=r"(r[2]), "=r"(r[3]) : "r"(addr));
}
__device__ __forceinline__ void ldmx4t(uint32_t* r, uint32_t addr) {
    asm volatile("ldmatrix.sync.aligned.m8n8.x4.trans.shared.b16 {%0,%1,%2,%3}, [%4];"
                 : "=r"(r[0]), "=r"(r[1]), "=r"(r[2]), "=r"(r[3]) : "r"(addr));
}
__device__ __forceinline__ void mma_hf(float* c, const uint32_t* a, const uint32_t* b) {
    asm volatile(
        "mma.sync.aligned.m16n8k16.row.col.f32.f16.f16.f32 "
        "{%0,%1,%2,%3}, {%4,%5,%6,%7}, {%8,%9}, {%0,%1,%2,%3};"
        : "+f"(c[0]), "+f"(c[1]), "+f"(c[2]), "+f"(c[3])
        : "r"(a[0]), "r"(a[1]), "r"(a[2]), "r"(a[3]), "r"(b[0]), "r"(b[1]));
}
__device__ __forceinline__ uint32_t ex2_f16x2(uint32_t x) {
    uint32_t r;
    asm("ex2.approx.f16x2 %0, %1;" : "=r"(r) : "r"(x));
    return r;
}
__device__ __forceinline__ void cpa16(uint32_t dst, const void* src) {
    asm volatile("cp.async.cg.shared.global [%0], [%1], 16;" :: "r"(dst), "l"(src));
}
// SW128 swizzle for 128-byte-pitch rows (attention smem only)
__device__ __forceinline__ uint32_t sw128(int row, int byteoff) {
    return (uint32_t)(row * 128 + (byteoff ^ ((row & 7) << 4)));
}
__device__ __forceinline__ void hfsplit2(float a, float b, uint32_t& hi, uint32_t& lo) {
    __half2 h, l;
    h.x = __float2half_rn(a);
    h.y = __float2half_rn(b);
    l.x = __float2half_rn(a - __half2float(h.x));
    l.y = __float2half_rn(b - __half2float(h.y));
    hi = *(uint32_t*)&h;
    lo = *(uint32_t*)&l;
}

// ---------------------------------------------------------------------------
// fp32 -> fp16 hi/lo split ; fp32 -> fp16 convert
// ---------------------------------------------------------------------------
__global__ __launch_bounds__(256) void split_f16(
    const float* __restrict__ in, __half* __restrict__ hi,
    __half* __restrict__ lo, int n4)
{
    int i = blockIdx.x * blockDim.x + threadIdx.x;
    if (i >= n4) return;
    float4 v = ((const float4*)in)[i];
    uint32_t h0, l0, h1, l1;
    hfsplit2(v.x, v.y, h0, l0);
    hfsplit2(v.z, v.w, h1, l1);
    ((uint2*)hi)[i] = make_uint2(h0, h1);
    ((uint2*)lo)[i] = make_uint2(l0, l1);
}
__global__ __launch_bounds__(256) void conv_f16(
    const float* __restrict__ in, __half* __restrict__ o16, int n4)
{
    int i = blockIdx.x * blockDim.x + threadIdx.x;
    if (i >= n4) return;
    float4 v = ((const float4*)in)[i];
    __half2 a = __floats2half2_rn(v.x, v.y);
    __half2 b = __floats2half2_rn(v.z, v.w);
    ((uint2*)o16)[i] = make_uint2(*(uint32_t*)&a, *(uint32_t*)&b);
}

// ---------------------------------------------------------------------------
// GEMM common geometry (R7-proven schedule:
//   { prefetch(c+1); wait_group 1; sync; mma(c); sync } )
// fp16 2-term: A = fp16 hi/lo, B = fp16 single.
// ---------------------------------------------------------------------------
#define GPAD_A 40
#define GPAD_B 136
#define STAGE_A (128 * GPAD_A)
#define STAGE_B (32 * GPAD_B)
#define OSTAGE_BYTES (2 * STAGE_A * 2 + STAGE_B * 2)   // Ah,Al + Bh
#define OGEMM_SMEM (2 * OSTAGE_BYTES)

// MODE 0: qkv epilogue -> g_Q16/K16/V16 ([tok][1024] fp16 each).
// MODE 1: plain fp32 C.
template<int MODE>
__global__ __launch_bounds__(256, 2) void tc_gemm_h2(
    const __half* __restrict__ Ah, const __half* __restrict__ Al,
    const __half* __restrict__ Bh,
    float* __restrict__ C, int M, int N, int K)
{
    extern __shared__ __half smo[];
    const uint32_t smb = smem_u32(smo);

    const int tid  = threadIdx.x;
    const int lane = tid & 31;
    const int wid  = tid >> 5;
    const int wm   = wid & 1;
    const int wn   = wid >> 1;
    const int crow = blockIdx.y * 128;
    const int ccol = blockIdx.x * 128;

    const int arow0 = tid >> 2;
    const int ach   = (tid & 3) * 8;
    const int brow0 = tid >> 4;
    const int bch   = (tid & 15) * 8;

    auto prefetch = [&](int c) {
        const uint32_t sb = smb + (uint32_t)(c & 1) * OSTAGE_BYTES;
        const size_t ka = (size_t)c * 32;
        #pragma unroll
        for (int j = 0; j < 2; j++) {
            int row = arow0 + j * 64;
            const __half* sh = Ah + (size_t)(crow + row) * K + ka + ach;
            const __half* sl = Al + (size_t)(crow + row) * K + ka + ach;
            uint32_t d = sb + (uint32_t)(row * GPAD_A + ach) * 2;
            cpa16(d, sh);
            cpa16(d + STAGE_A * 2, sl);
        }
        #pragma unroll
        for (int j = 0; j < 2; j++) {
            int row = brow0 + j * 16;
            cpa16(sb + (uint32_t)(2 * STAGE_A + row * GPAD_B + bch) * 2,
                  Bh + (size_t)(ka + row) * N + ccol + bch);
        }
        asm volatile("cp.async.commit_group;" ::: "memory");
    };

    const int aRowBase = wm * 64 + (lane & 15);
    const int aColOff  = (lane >> 4) * 8;
    const int bKrow    = (lane & 7) + ((lane >> 3) & 1) * 8;
    const int bNBase   = wn * 32 + (lane >> 4) * 8;

    float acc[4][4][4];
    #pragma unroll
    for (int i = 0; i < 4; i++)
        #pragma unroll
        for (int j = 0; j < 4; j++)
            #pragma unroll
            for (int r = 0; r < 4; r++) acc[i][j][r] = 0.f;

    const int nchunks = K >> 5;
    prefetch(0);

    for (int c = 0; c < nchunks; c++) {
        if (c + 1 < nchunks) {
            prefetch(c + 1);
            asm volatile("cp.async.wait_group 1;" ::: "memory");
        } else {
            asm volatile("cp.async.wait_group 0;" ::: "memory");
        }
        __syncthreads();

        const uint32_t sb  = smb + (uint32_t)(c & 1) * OSTAGE_BYTES;
        const uint32_t bAh = sb;
        const uint32_t bAl = sb + STAGE_A * 2;
        const uint32_t bBh = sb + 2 * STAGE_A * 2;

        #pragma unroll
        for (int ks = 0; ks < 2; ks++) {
            uint32_t ah[4][4], al[4][4], bh[2][4];
            #pragma unroll
            for (int mf = 0; mf < 4; mf++) {
                uint32_t off = (uint32_t)((aRowBase + mf * 16) * GPAD_A + ks * 16 + aColOff) * 2;
                ldmx4(ah[mf], bAh + off);
                ldmx4(al[mf], bAl + off);
            }
            #pragma unroll
            for (int nf2 = 0; nf2 < 2; nf2++) {
                uint32_t off = (uint32_t)((ks * 16 + bKrow) * GPAD_B + bNBase + nf2 * 16) * 2;
                ldmx4t(bh[nf2], bBh + off);
            }
            #pragma unroll
            for (int mf = 0; mf < 4; mf++)
                #pragma unroll
                for (int nf = 0; nf < 4; nf++) {
                    const uint32_t* bhp = &bh[nf >> 1][(nf & 1) * 2];
                    mma_hf(acc[mf][nf], ah[mf], bhp);
                    mma_hf(acc[mf][nf], al[mf], bhp);
                }
        }
        __syncthreads();
    }

    if (MODE == 1) {
        #pragma unroll
        for (int mf = 0; mf < 4; mf++) {
            int row0 = crow + wm * 64 + mf * 16 + (lane >> 2);
            #pragma unroll
            for (int nf = 0; nf < 4; nf++) {
                int col = ccol + wn * 32 + nf * 8 + (lane & 3) * 2;
                *(float2*)&C[(size_t)row0 * N + col] =
                    make_float2(acc[mf][nf][0], acc[mf][nf][1]);
                *(float2*)&C[(size_t)(row0 + 8) * N + col] =
                    make_float2(acc[mf][nf][2], acc[mf][nf][3]);
            }
        }
    } else {
        // qkv epilogue: n -> sect (q/k/v) + col (h*64+d), [tok][1024], fp16
        const int nbase = ccol + wn * 32;
        const int sect  = nbase >> 10;
        __half* dst = (sect == 0) ? g_Q16 : (sect == 1) ? g_K16 : g_V16;
        #pragma unroll
        for (int mf = 0; mf < 4; mf++) {
            int m0 = crow + wm * 64 + mf * 16 + (lane >> 2);
            #pragma unroll
            for (int nf = 0; nf < 4; nf++) {
                int col = (nbase + nf * 8 + (lane & 3) * 2) & 1023;
                #pragma unroll
                for (int r2 = 0; r2 < 2; r2++) {
                    size_t di = (size_t)(m0 + r2 * 8) * 1024 + col;
                    __half2 hv = __floats2half2_rn(acc[mf][nf][r2 * 2],
                                                   acc[mf][nf][r2 * 2 + 1]);
                    *(__half2*)&dst[di] = hv;
                }
            }
        }
    }
}

// ---------------------------------------------------------------------------
// Tensor-core causal flash attention, all-fp16 operands.
// S = Q K^T single-term fp16 (error ~4.8e-4 on logit scale, within budget).
// smem: Q 16K | K 8K | V 8K = 32 KB, SW128 128B rows.
// ---------------------------------------------------------------------------
#define ATTN_SMEM (16384 + 8192 * 2)

__global__ __launch_bounds__(256, 2) void flash_attn_tc6(
    const __half* __restrict__ Q16, const __half* __restrict__ K16,
    const __half* __restrict__ V16,
    __half* __restrict__ oh, __half* __restrict__ ol)
{
    extern __shared__ char smraw[];
    char* pQ = smraw;
    char* pK = smraw + 16384;
    char* pV = pK + 8192;

    const int tid = threadIdx.x, lane = tid & 31, wid = tid >> 5;
    const int b  = blockIdx.y >> 4;
    const int h  = blockIdx.y & 15;
    const int qt = gridDim.x - 1 - blockIdx.x;   // heavy tiles first
    const int q0 = qt * 128;

    const size_t rbase = (size_t)b * 2048;
    const int    cbase = h * 64;

    // Load Q tile (128 rows x 128B), swizzled
    #pragma unroll
    for (int i = 0; i < 4; i++) {
        int li = i * 256 + tid;
        int r = li >> 3, ch = li & 7;
        size_t gi = (rbase + q0 + r) * 1024 + cbase + ch * 8;
        *(uint4*)(pQ + sw128(r, ch * 16)) = *(const uint4*)(Q16 + gi);
    }

    const uint32_t aQ = smem_u32(pQ);
    const uint32_t aK = smem_u32(pK);
    const uint32_t aV = smem_u32(pV);

    const int rowQ = wid * 16 + (lane & 15);
    const int colB = (lane >> 4) * 16;              // bytes
    const int kRow = lane & 15;
    const int vRow = (lane & 7) + ((lane >> 3) & 1) * 8;

    float accO[8][4];
    #pragma unroll
    for (int i = 0; i < 8; i++)
        #pragma unroll
        for (int r = 0; r < 4; r++) accO[i][r] = 0.f;
    float lr = 0.f, lr8 = 0.f;

    const int rowbase = q0 + wid * 16;
    const int nkt = 2 * qt + 2;
    const float csc = 0.1803368802f;   // log2(e)/8

    for (int kt = 0; kt < nkt; kt++) {
        const int kv0 = kt * 64;
        __syncthreads();

        // Load K and V tiles (64 x 128B each)
        #pragma unroll
        for (int i = 0; i < 2; i++) {
            int li = i * 256 + tid;
            int r = li >> 3, ch = li & 7;
            size_t gi = (rbase + kv0 + r) * 1024 + cbase + ch * 8;
            uint32_t so = sw128(r, ch * 16);
            *(uint4*)(pK + so) = *(const uint4*)(K16 + gi);
            *(uint4*)(pV + so) = *(const uint4*)(V16 + gi);
        }
        __syncthreads();

        // --- S = Q K^T (single fp16 term) ---
        float S[8][4];
        #pragma unroll
        for (int i = 0; i < 8; i++)
            #pragma unroll
            for (int r = 0; r < 4; r++) S[i][r] = 0.f;

        #pragma unroll
        for (int ks = 0; ks < 4; ks++) {
            uint32_t aq[4];
            ldmx4(aq, aQ + sw128(rowQ, ks * 32 + colB));
            #pragma unroll
            for (int g = 0; g < 4; g++) {
                uint32_t kk[4];
                ldmx4(kk, aK + sw128(g * 16 + kRow, ks * 32 + colB));
                uint32_t be[2] = {kk[0], kk[2]};
                uint32_t bo[2] = {kk[1], kk[3]};
                mma_hf(S[2*g],   aq, be);
                mma_hf(S[2*g+1], aq, bo);
            }
        }

        // --- causal mask ---
        if (kv0 + 63 > rowbase) {
            int r0 = rowbase + (lane >> 2);
            #pragma unroll
            for (int nf = 0; nf < 8; nf++) {
                int c0 = kv0 + nf * 8 + (lane & 3) * 2;
                if (c0 > r0)          S[nf][0] = -1e5f;
                if (c0 + 1 > r0)      S[nf][1] = -1e5f;
                if (c0 > r0 + 8)      S[nf][2] = -1e5f;
                if (c0 + 1 > r0 + 8)  S[nf][3] = -1e5f;
            }
        }

        // --- P = exp(S) (fp16 A-frag layout) + row sums ---
        uint32_t P[8][2];
        #pragma unroll
        for (int nf = 0; nf < 8; nf++) {
            __half2 h0 = __floats2half2_rn(S[nf][0] * csc, S[nf][1] * csc);
            __half2 h1 = __floats2half2_rn(S[nf][2] * csc, S[nf][3] * csc);
            uint32_t p0 = ex2_f16x2(*(uint32_t*)&h0);
            uint32_t p1 = ex2_f16x2(*(uint32_t*)&h1);
            P[nf][0] = p0;
            P[nf][1] = p1;
            float2 f0 = __half22float2(*(__half2*)&p0);
            float2 f1 = __half22float2(*(__half2*)&p1);
            lr  += f0.x + f0.y;
            lr8 += f1.x + f1.y;
        }

        // --- O += P @ V ---
        #pragma unroll
        for (int j = 0; j < 4; j++) {
            uint32_t a[4] = { P[2*j][0], P[2*j][1], P[2*j+1][0], P[2*j+1][1] };
            int r = j * 16 + vRow;
            #pragma unroll
            for (int dg = 0; dg < 2; dg++) {
                uint32_t vv[4], vv2[4];
                ldmx4t(vv,  aV + sw128(r, dg * 64 + colB));
                ldmx4t(vv2, aV + sw128(r, dg * 64 + 32 + colB));
                mma_hf(accO[4*dg + 0], a, &vv[0]);
                mma_hf(accO[4*dg + 1], a, &vv[2]);
                mma_hf(accO[4*dg + 2], a, &vv2[0]);
                mma_hf(accO[4*dg + 3], a, &vv2[2]);
            }
        }
    }

    lr  += __shfl_xor_sync(0xffffffffu, lr, 1);
    lr  += __shfl_xor_sync(0xffffffffu, lr, 2);
    lr8 += __shfl_xor_sync(0xffffffffu, lr8, 1);
    lr8 += __shfl_xor_sync(0xffffffffu, lr8, 2);
    const float inv  = 1.f / lr;
    const float inv8 = 1.f / lr8;

    const int grow = b * TSEQ + q0 + wid * 16 + (lane >> 2);
    #pragma unroll
    for (int dg = 0; dg < 8; dg++) {
        int col = cbase + dg * 8 + (lane & 3) * 2;
        uint32_t hi, lo;
        hfsplit2(accO[dg][0] * inv, accO[dg][1] * inv, hi, lo);
        size_t i0 = (size_t)grow * DMODEL + col;
        *(uint32_t*)&oh[i0] = hi;
        *(uint32_t*)&ol[i0] = lo;
        hfsplit2(accO[dg][2] * inv8, accO[dg][3] * inv8, hi, lo);
        size_t i1 = (size_t)(grow + 8) * DMODEL + col;
        *(uint32_t*)&oh[i1] = hi;
        *(uint32_t*)&ol[i1] = lo;
    }
}

// ---------------------------------------------------------------------------
extern "C" void kernel_launch(void* const* d_in, const int* in_sizes, int n_in,
                              void* d_out, int out_size)
{
    const float* x     = (const float*)d_in[0];
    const float* W_qkv = (const float*)d_in[1];
    const float* W_out = (const float*)d_in[2];
    float* out = (float*)d_out;

    __half *x16h, *x16l, *wq16, *wo16, *ah, *al, *Q16, *K16, *V16;
    cudaGetSymbolAddress((void**)&x16h, g_x16h);
    cudaGetSymbolAddress((void**)&x16l, g_x16l);
    cudaGetSymbolAddress((void**)&wq16, g_wq16);
    cudaGetSymbolAddress((void**)&wo16, g_wo16);
    cudaGetSymbolAddress((void**)&ah,   g_ah);
    cudaGetSymbolAddress((void**)&al,   g_al);
    cudaGetSymbolAddress((void**)&Q16,  g_Q16);
    cudaGetSymbolAddress((void**)&K16,  g_K16);
    cudaGetSymbolAddress((void**)&V16,  g_V16);

    cudaFuncSetAttribute(tc_gemm_h2<0>, cudaFuncAttributeMaxDynamicSharedMemorySize,
                         OGEMM_SMEM);
    cudaFuncSetAttribute(tc_gemm_h2<1>, cudaFuncAttributeMaxDynamicSharedMemorySize,
                         OGEMM_SMEM);
    cudaFuncSetAttribute(flash_attn_tc6, cudaFuncAttributeMaxDynamicSharedMemorySize,
                         ATTN_SMEM);

    // 0) Split / convert inputs
    {
        int n4 = MTOK * DMODEL / 4;
        split_f16<<<(n4 + 255) / 256, 256>>>(x, x16h, x16l, n4);
        int w4 = DMODEL * QKV_N / 4;
        conv_f16<<<(w4 + 255) / 256, 256>>>(W_qkv, wq16, w4);
        int o4 = DMODEL * DMODEL / 4;
        conv_f16<<<(o4 + 255) / 256, 256>>>(W_out, wo16, o4);
    }

    // 1) QKV projection (fp16 2-term) -> Q/K/V fp16, [tok][1024]
    tc_gemm_h2<0><<<dim3(QKV_N / 128, MTOK / 128), 256, OGEMM_SMEM>>>(
        x16h, x16l, wq16, nullptr, MTOK, QKV_N, DMODEL);

    // 2) Causal flash attention -> fp16 hi/lo output
    flash_attn_tc6<<<dim3(TSEQ / 128, BATCH * NHEADS), 256, ATTN_SMEM>>>(
        Q16, K16, V16, ah, al);

    // 3) Output projection: fp16 2-term (fp32 out)
    tc_gemm_h2<1><<<dim3(DMODEL / 128, MTOK / 128), 256, OGEMM_SMEM>>>(
        ah, al, wo16, out, MTOK, DMODEL, DMODEL);
}

// round 12
// speedup vs baseline: 2.5712x; 1.2372x over previous
#include <cuda_runtime.h>
#include <cuda_bf16.h>
#include <cuda_fp16.h>
#include <math.h>
#include <stdint.h>

// Problem constants
#define BATCH   4
#define TSEQ    2048
#define DMODEL  1024
#define NHEADS  16
#define DHEAD   64
#define MTOK    (BATCH * TSEQ)       // 8192 rows
#define QKV_N   (3 * DMODEL)         // 3072

// Scratch (no cudaMalloc). Per-token layouts are [tok][1024] (h*64+d).
__device__ __half g_Q16[(size_t)MTOK * DMODEL];
__device__ __half g_K16[(size_t)MTOK * DMODEL];
__device__ __half g_V16[(size_t)MTOK * DMODEL];
__device__ __half g_x16[(size_t)MTOK * DMODEL];
__device__ __half g_wq16[(size_t)DMODEL * QKV_N];
__device__ __half g_wo16[(size_t)DMODEL * DMODEL];
__device__ __half g_ah[(size_t)MTOK * DMODEL];       // attn out fp16 hi
__device__ __half g_al[(size_t)MTOK * DMODEL];       // attn out fp16 lo

// ---------------------------------------------------------------------------
// PTX helpers
// ---------------------------------------------------------------------------
__device__ __forceinline__ uint32_t smem_u32(const void* p) {
    uint32_t a;
    asm("{ .reg .u64 t; cvta.to.shared.u64 t, %1; cvt.u32.u64 %0, t; }"
        : "=r"(a) : "l"(p));
    return a;
}
__device__ __forceinline__ void ldmx4(uint32_t* r, uint32_t addr) {
    asm volatile("ldmatrix.sync.aligned.m8n8.x4.shared.b16 {%0,%1,%2,%3}, [%4];"
                 : "=r"(r[0]), "=r"(r[1]), "=r"(r[2]), "=r"(r[3]) : "r"(addr));
}
__device__ __forceinline__ void ldmx4t(uint32_t* r, uint32_t addr) {
    asm volatile("ldmatrix.sync.aligned.m8n8.x4.trans.shared.b16 {%0,%1,%2,%3}, [%4];"
                 : "=r"(r[0]), "=r"(r[1]), "=r"(r[2]), "=r"(r[3]) : "r"(addr));
}
__device__ __forceinline__ void mma_hf(float* c, const uint32_t* a, const uint32_t* b) {
    asm volatile(
        "mma.sync.aligned.m16n8k16.row.col.f32.f16.f16.f32 "
        "{%0,%1,%2,%3}, {%4,%5,%6,%7}, {%8,%9}, {%0,%1,%2,%3};"
        : "+f"(c[0]), "+f"(c[1]), "+f"(c[2]), "+f"(c[3])
        : "r"(a[0]), "r"(a[1]), "r"(a[2]), "r"(a[3]), "r"(b[0]), "r"(b[1]));
}
__device__ __forceinline__ uint32_t ex2_f16x2(uint32_t x) {
    uint32_t r;
    asm("ex2.approx.f16x2 %0, %1;" : "=r"(r) : "r"(x));
    return r;
}
__device__ __forceinline__ void cpa16(uint32_t dst, const void* src) {
    asm volatile("cp.async.cg.shared.global [%0], [%1], 16;" :: "r"(dst), "l"(src));
}
// SW128 swizzle for 128-byte-pitch rows (attention smem only)
__device__ __forceinline__ uint32_t sw128(int row, int byteoff) {
    return (uint32_t)(row * 128 + (byteoff ^ ((row & 7) << 4)));
}
__device__ __forceinline__ void hfsplit2(float a, float b, uint32_t& hi, uint32_t& lo) {
    __half2 h, l;
    h.x = __float2half_rn(a);
    h.y = __float2half_rn(b);
    l.x = __float2half_rn(a - __half2float(h.x));
    l.y = __float2half_rn(b - __half2float(h.y));
    hi = *(uint32_t*)&h;
    lo = *(uint32_t*)&l;
}

// ---------------------------------------------------------------------------
// fp32 -> fp16 convert
// ---------------------------------------------------------------------------
__global__ __launch_bounds__(256) void conv_f16(
    const float* __restrict__ in, __half* __restrict__ o16, int n4)
{
    int i = blockIdx.x * blockDim.x + threadIdx.x;
    if (i >= n4) return;
    float4 v = ((const float4*)in)[i];
    __half2 a = __floats2half2_rn(v.x, v.y);
    __half2 b = __floats2half2_rn(v.z, v.w);
    ((uint2*)o16)[i] = make_uint2(*(uint32_t*)&a, *(uint32_t*)&b);
}

// ---------------------------------------------------------------------------
// Common GEMM geometry
// ---------------------------------------------------------------------------
#define GPAD_A 40
#define GPAD_B 136
#define STAGE_A (128 * GPAD_A)
#define STAGE_B (32 * GPAD_B)

// ---------------------------------------------------------------------------
// QKV GEMM: single fp16 A-term, 3-stage cp.async pipeline.
//   iter c = { [prefetch(c+2); wait 2 | wait 1 | wait 0]; sync; mma(c); sync }
// (prefetch-before-wait ordering preserved; trailing sync protects reuse.)
// Epilogue scatters Q/K/V fp16 into [tok][1024].
// ---------------------------------------------------------------------------
#define QSTAGE_BYTES (STAGE_A * 2 + STAGE_B * 2)       // A + B = 18944
#define QGEMM_SMEM (3 * QSTAGE_BYTES)                  // 56832

__global__ __launch_bounds__(256, 2) void tc_gemm_qkv1(
    const __half* __restrict__ Ah, const __half* __restrict__ Bh,
    int M, int N, int K)
{
    extern __shared__ __half smq[];
    const uint32_t smb = smem_u32(smq);

    const int tid  = threadIdx.x;
    const int lane = tid & 31;
    const int wid  = tid >> 5;
    const int wm   = wid & 1;
    const int wn   = wid >> 1;
    const int crow = blockIdx.y * 128;
    const int ccol = blockIdx.x * 128;

    const int arow0 = tid >> 2;
    const int ach   = (tid & 3) * 8;
    const int brow0 = tid >> 4;
    const int bch   = (tid & 15) * 8;

    auto prefetch = [&](int c, int s) {
        const uint32_t sb = smb + (uint32_t)s * QSTAGE_BYTES;
        const size_t ka = (size_t)c * 32;
        #pragma unroll
        for (int j = 0; j < 2; j++) {
            int row = arow0 + j * 64;
            cpa16(sb + (uint32_t)(row * GPAD_A + ach) * 2,
                  Ah + (size_t)(crow + row) * K + ka + ach);
        }
        #pragma unroll
        for (int j = 0; j < 2; j++) {
            int row = brow0 + j * 16;
            cpa16(sb + (uint32_t)(STAGE_A + row * GPAD_B + bch) * 2,
                  Bh + (size_t)(ka + row) * N + ccol + bch);
        }
        asm volatile("cp.async.commit_group;" ::: "memory");
    };

    const int aRowBase = wm * 64 + (lane & 15);
    const int aColOff  = (lane >> 4) * 8;
    const int bKrow    = (lane & 7) + ((lane >> 3) & 1) * 8;
    const int bNBase   = wn * 32 + (lane >> 4) * 8;

    float acc[4][4][4];
    #pragma unroll
    for (int i = 0; i < 4; i++)
        #pragma unroll
        for (int j = 0; j < 4; j++)
            #pragma unroll
            for (int r = 0; r < 4; r++) acc[i][j][r] = 0.f;

    const int nchunks = K >> 5;   // 32
    prefetch(0, 0);
    prefetch(1, 1);

    int s = 0;        // buffer of chunk c
    int s2 = 2;       // buffer for chunk c+2
    for (int c = 0; c < nchunks; c++) {
        if (c + 2 < nchunks) {
            prefetch(c + 2, s2);
            asm volatile("cp.async.wait_group 2;" ::: "memory");
        } else if (c + 1 < nchunks) {
            asm volatile("cp.async.wait_group 1;" ::: "memory");
        } else {
            asm volatile("cp.async.wait_group 0;" ::: "memory");
        }
        __syncthreads();

        const uint32_t sb  = smb + (uint32_t)s * QSTAGE_BYTES;
        const uint32_t bAh = sb;
        const uint32_t bBh = sb + STAGE_A * 2;

        #pragma unroll
        for (int ks = 0; ks < 2; ks++) {
            uint32_t ah[4][4], bh[2][4];
            #pragma unroll
            for (int mf = 0; mf < 4; mf++) {
                uint32_t off = (uint32_t)((aRowBase + mf * 16) * GPAD_A + ks * 16 + aColOff) * 2;
                ldmx4(ah[mf], bAh + off);
            }
            #pragma unroll
            for (int nf2 = 0; nf2 < 2; nf2++) {
                uint32_t off = (uint32_t)((ks * 16 + bKrow) * GPAD_B + bNBase + nf2 * 16) * 2;
                ldmx4t(bh[nf2], bBh + off);
            }
            #pragma unroll
            for (int mf = 0; mf < 4; mf++)
                #pragma unroll
                for (int nf = 0; nf < 4; nf++)
                    mma_hf(acc[mf][nf], ah[mf], &bh[nf >> 1][(nf & 1) * 2]);
        }
        __syncthreads();

        s  = (s  == 2) ? 0 : s  + 1;
        s2 = (s2 == 2) ? 0 : s2 + 1;
    }

    // qkv epilogue: n -> sect (q/k/v) + col (h*64+d), [tok][1024], fp16
    const int nbase = ccol + wn * 32;
    const int sect  = nbase >> 10;
    __half* dst = (sect == 0) ? g_Q16 : (sect == 1) ? g_K16 : g_V16;
    #pragma unroll
    for (int mf = 0; mf < 4; mf++) {
        int m0 = crow + wm * 64 + mf * 16 + (lane >> 2);
        #pragma unroll
        for (int nf = 0; nf < 4; nf++) {
            int col = (nbase + nf * 8 + (lane & 3) * 2) & 1023;
            #pragma unroll
            for (int r2 = 0; r2 < 2; r2++) {
                size_t di = (size_t)(m0 + r2 * 8) * 1024 + col;
                __half2 hv = __floats2half2_rn(acc[mf][nf][r2 * 2],
                                               acc[mf][nf][r2 * 2 + 1]);
                *(__half2*)&dst[di] = hv;
            }
        }
    }
}

// ---------------------------------------------------------------------------
// Output GEMM: fp16 2-term A (attn out hi/lo), B fp16 single. R10-proven.
// ---------------------------------------------------------------------------
#define OSTAGE_BYTES (2 * STAGE_A * 2 + STAGE_B * 2)   // Ah,Al + Bh
#define OGEMM_SMEM (2 * OSTAGE_BYTES)

__global__ __launch_bounds__(256, 2) void tc_gemm_out(
    const __half* __restrict__ Ah, const __half* __restrict__ Al,
    const __half* __restrict__ Bh,
    float* __restrict__ C, int M, int N, int K)
{
    extern __shared__ __half smo[];
    const uint32_t smb = smem_u32(smo);

    const int tid  = threadIdx.x;
    const int lane = tid & 31;
    const int wid  = tid >> 5;
    const int wm   = wid & 1;
    const int wn   = wid >> 1;
    const int crow = blockIdx.y * 128;
    const int ccol = blockIdx.x * 128;

    const int arow0 = tid >> 2;
    const int ach   = (tid & 3) * 8;
    const int brow0 = tid >> 4;
    const int bch   = (tid & 15) * 8;

    auto prefetch = [&](int c) {
        const uint32_t sb = smb + (uint32_t)(c & 1) * OSTAGE_BYTES;
        const size_t ka = (size_t)c * 32;
        #pragma unroll
        for (int j = 0; j < 2; j++) {
            int row = arow0 + j * 64;
            const __half* sh = Ah + (size_t)(crow + row) * K + ka + ach;
            const __half* sl = Al + (size_t)(crow + row) * K + ka + ach;
            uint32_t d = sb + (uint32_t)(row * GPAD_A + ach) * 2;
            cpa16(d, sh);
            cpa16(d + STAGE_A * 2, sl);
        }
        #pragma unroll
        for (int j = 0; j < 2; j++) {
            int row = brow0 + j * 16;
            cpa16(sb + (uint32_t)(2 * STAGE_A + row * GPAD_B + bch) * 2,
                  Bh + (size_t)(ka + row) * N + ccol + bch);
        }
        asm volatile("cp.async.commit_group;" ::: "memory");
    };

    const int aRowBase = wm * 64 + (lane & 15);
    const int aColOff  = (lane >> 4) * 8;
    const int bKrow    = (lane & 7) + ((lane >> 3) & 1) * 8;
    const int bNBase   = wn * 32 + (lane >> 4) * 8;

    float acc[4][4][4];
    #pragma unroll
    for (int i = 0; i < 4; i++)
        #pragma unroll
        for (int j = 0; j < 4; j++)
            #pragma unroll
            for (int r = 0; r < 4; r++) acc[i][j][r] = 0.f;

    const int nchunks = K >> 5;
    prefetch(0);

    for (int c = 0; c < nchunks; c++) {
        if (c + 1 < nchunks) {
            prefetch(c + 1);
            asm volatile("cp.async.wait_group 1;" ::: "memory");
        } else {
            asm volatile("cp.async.wait_group 0;" ::: "memory");
        }
        __syncthreads();

        const uint32_t sb  = smb + (uint32_t)(c & 1) * OSTAGE_BYTES;
        const uint32_t bAh = sb;
        const uint32_t bAl = sb + STAGE_A * 2;
        const uint32_t bBh = sb + 2 * STAGE_A * 2;

        #pragma unroll
        for (int ks = 0; ks < 2; ks++) {
            uint32_t ah[4][4], al[4][4], bh[2][4];
            #pragma unroll
            for (int mf = 0; mf < 4; mf++) {
                uint32_t off = (uint32_t)((aRowBase + mf * 16) * GPAD_A + ks * 16 + aColOff) * 2;
                ldmx4(ah[mf], bAh + off);
                ldmx4(al[mf], bAl + off);
            }
            #pragma unroll
            for (int nf2 = 0; nf2 < 2; nf2++) {
                uint32_t off = (uint32_t)((ks * 16 + bKrow) * GPAD_B + bNBase + nf2 * 16) * 2;
                ldmx4t(bh[nf2], bBh + off);
            }
            #pragma unroll
            for (int mf = 0; mf < 4; mf++)
                #pragma unroll
                for (int nf = 0; nf < 4; nf++) {
                    const uint32_t* bhp = &bh[nf >> 1][(nf & 1) * 2];
                    mma_hf(acc[mf][nf], ah[mf], bhp);
                    mma_hf(acc[mf][nf], al[mf], bhp);
                }
        }
        __syncthreads();
    }

    #pragma unroll
    for (int mf = 0; mf < 4; mf++) {
        int row0 = crow + wm * 64 + mf * 16 + (lane >> 2);
        #pragma unroll
        for (int nf = 0; nf < 4; nf++) {
            int col = ccol + wn * 32 + nf * 8 + (lane & 3) * 2;
            *(float2*)&C[(size_t)row0 * N + col] =
                make_float2(acc[mf][nf][0], acc[mf][nf][1]);
            *(float2*)&C[(size_t)(row0 + 8) * N + col] =
                make_float2(acc[mf][nf][2], acc[mf][nf][3]);
        }
    }
}

// ---------------------------------------------------------------------------
// Tensor-core causal flash attention, all-fp16 (unchanged from R11).
// smem: Q 16K | K 8K | V 8K = 32 KB, SW128 128B rows.
// ---------------------------------------------------------------------------
#define ATTN_SMEM (16384 + 8192 * 2)

__global__ __launch_bounds__(256, 2) void flash_attn_tc6(
    const __half* __restrict__ Q16, const __half* __restrict__ K16,
    const __half* __restrict__ V16,
    __half* __restrict__ oh, __half* __restrict__ ol)
{
    extern __shared__ char smraw[];
    char* pQ = smraw;
    char* pK = smraw + 16384;
    char* pV = pK + 8192;

    const int tid = threadIdx.x, lane = tid & 31, wid = tid >> 5;
    const int b  = blockIdx.y >> 4;
    const int h  = blockIdx.y & 15;
    const int qt = gridDim.x - 1 - blockIdx.x;   // heavy tiles first
    const int q0 = qt * 128;

    const size_t rbase = (size_t)b * 2048;
    const int    cbase = h * 64;

    #pragma unroll
    for (int i = 0; i < 4; i++) {
        int li = i * 256 + tid;
        int r = li >> 3, ch = li & 7;
        size_t gi = (rbase + q0 + r) * 1024 + cbase + ch * 8;
        *(uint4*)(pQ + sw128(r, ch * 16)) = *(const uint4*)(Q16 + gi);
    }

    const uint32_t aQ = smem_u32(pQ);
    const uint32_t aK = smem_u32(pK);
    const uint32_t aV = smem_u32(pV);

    const int rowQ = wid * 16 + (lane & 15);
    const int colB = (lane >> 4) * 16;              // bytes
    const int kRow = lane & 15;
    const int vRow = (lane & 7) + ((lane >> 3) & 1) * 8;

    float accO[8][4];
    #pragma unroll
    for (int i = 0; i < 8; i++)
        #pragma unroll
        for (int r = 0; r < 4; r++) accO[i][r] = 0.f;
    float lr = 0.f, lr8 = 0.f;

    const int rowbase = q0 + wid * 16;
    const int nkt = 2 * qt + 2;
    const float csc = 0.1803368802f;   // log2(e)/8

    for (int kt = 0; kt < nkt; kt++) {
        const int kv0 = kt * 64;
        __syncthreads();

        #pragma unroll
        for (int i = 0; i < 2; i++) {
            int li = i * 256 + tid;
            int r = li >> 3, ch = li & 7;
            size_t gi = (rbase + kv0 + r) * 1024 + cbase + ch * 8;
            uint32_t so = sw128(r, ch * 16);
            *(uint4*)(pK + so) = *(const uint4*)(K16 + gi);
            *(uint4*)(pV + so) = *(const uint4*)(V16 + gi);
        }
        __syncthreads();

        float S[8][4];
        #pragma unroll
        for (int i = 0; i < 8; i++)
            #pragma unroll
            for (int r = 0; r < 4; r++) S[i][r] = 0.f;

        #pragma unroll
        for (int ks = 0; ks < 4; ks++) {
            uint32_t aq[4];
            ldmx4(aq, aQ + sw128(rowQ, ks * 32 + colB));
            #pragma unroll
            for (int g = 0; g < 4; g++) {
                uint32_t kk[4];
                ldmx4(kk, aK + sw128(g * 16 + kRow, ks * 32 + colB));
                uint32_t be[2] = {kk[0], kk[2]};
                uint32_t bo[2] = {kk[1], kk[3]};
                mma_hf(S[2*g],   aq, be);
                mma_hf(S[2*g+1], aq, bo);
            }
        }

        if (kv0 + 63 > rowbase) {
            int r0 = rowbase + (lane >> 2);
            #pragma unroll
            for (int nf = 0; nf < 8; nf++) {
                int c0 = kv0 + nf * 8 + (lane & 3) * 2;
                if (c0 > r0)          S[nf][0] = -1e5f;
                if (c0 + 1 > r0)      S[nf][1] = -1e5f;
                if (c0 > r0 + 8)      S[nf][2] = -1e5f;
                if (c0 + 1 > r0 + 8)  S[nf][3] = -1e5f;
            }
        }

        uint32_t P[8][2];
        #pragma unroll
        for (int nf = 0; nf < 8; nf++) {
            __half2 h0 = __floats2half2_rn(S[nf][0] * csc, S[nf][1] * csc);
            __half2 h1 = __floats2half2_rn(S[nf][2] * csc, S[nf][3] * csc);
            uint32_t p0 = ex2_f16x2(*(uint32_t*)&h0);
            uint32_t p1 = ex2_f16x2(*(uint32_t*)&h1);
            P[nf][0] = p0;
            P[nf][1] = p1;
            float2 f0 = __half22float2(*(__half2*)&p0);
            float2 f1 = __half22float2(*(__half2*)&p1);
            lr  += f0.x + f0.y;
            lr8 += f1.x + f1.y;
        }

        #pragma unroll
        for (int j = 0; j < 4; j++) {
            uint32_t a[4] = { P[2*j][0], P[2*j][1], P[2*j+1][0], P[2*j+1][1] };
            int r = j * 16 + vRow;
            #pragma unroll
            for (int dg = 0; dg < 2; dg++) {
                uint32_t vv[4], vv2[4];
                ldmx4t(vv,  aV + sw128(r, dg * 64 + colB));
                ldmx4t(vv2, aV + sw128(r, dg * 64 + 32 + colB));
                mma_hf(accO[4*dg + 0], a, &vv[0]);
                mma_hf(accO[4*dg + 1], a, &vv[2]);
                mma_hf(accO[4*dg + 2], a, &vv2[0]);
                mma_hf(accO[4*dg + 3], a, &vv2[2]);
            }
        }
    }

    lr  += __shfl_xor_sync(0xffffffffu, lr, 1);
    lr  += __shfl_xor_sync(0xffffffffu, lr, 2);
    lr8 += __shfl_xor_sync(0xffffffffu, lr8, 1);
    lr8 += __shfl_xor_sync(0xffffffffu, lr8, 2);
    const float inv  = 1.f / lr;
    const float inv8 = 1.f / lr8;

    const int grow = b * TSEQ + q0 + wid * 16 + (lane >> 2);
    #pragma unroll
    for (int dg = 0; dg < 8; dg++) {
        int col = cbase + dg * 8 + (lane & 3) * 2;
        uint32_t hi, lo;
        hfsplit2(accO[dg][0] * inv, accO[dg][1] * inv, hi, lo);
        size_t i0 = (size_t)grow * DMODEL + col;
        *(uint32_t*)&oh[i0] = hi;
        *(uint32_t*)&ol[i0] = lo;
        hfsplit2(accO[dg][2] * inv8, accO[dg][3] * inv8, hi, lo);
        size_t i1 = (size_t)(grow + 8) * DMODEL + col;
        *(uint32_t*)&oh[i1] = hi;
        *(uint32_t*)&ol[i1] = lo;
    }
}

// ---------------------------------------------------------------------------
extern "C" void kernel_launch(void* const* d_in, const int* in_sizes, int n_in,
                              void* d_out, int out_size)
{
    const float* x     = (const float*)d_in[0];
    const float* W_qkv = (const float*)d_in[1];
    const float* W_out = (const float*)d_in[2];
    float* out = (float*)d_out;

    __half *x16, *wq16, *wo16, *ah, *al, *Q16, *K16, *V16;
    cudaGetSymbolAddress((void**)&x16,  g_x16);
    cudaGetSymbolAddress((void**)&wq16, g_wq16);
    cudaGetSymbolAddress((void**)&wo16, g_wo16);
    cudaGetSymbolAddress((void**)&ah,   g_ah);
    cudaGetSymbolAddress((void**)&al,   g_al);
    cudaGetSymbolAddress((void**)&Q16,  g_Q16);
    cudaGetSymbolAddress((void**)&K16,  g_K16);
    cudaGetSymbolAddress((void**)&V16,  g_V16);

    cudaFuncSetAttribute(tc_gemm_qkv1, cudaFuncAttributeMaxDynamicSharedMemorySize,
                         QGEMM_SMEM);
    cudaFuncSetAttribute(tc_gemm_out, cudaFuncAttributeMaxDynamicSharedMemorySize,
                         OGEMM_SMEM);
    cudaFuncSetAttribute(flash_attn_tc6, cudaFuncAttributeMaxDynamicSharedMemorySize,
                         ATTN_SMEM);

    // 0) Convert inputs to fp16
    {
        int n4 = MTOK * DMODEL / 4;
        conv_f16<<<(n4 + 255) / 256, 256>>>(x, x16, n4);
        int w4 = DMODEL * QKV_N / 4;
        conv_f16<<<(w4 + 255) / 256, 256>>>(W_qkv, wq16, w4);
        int o4 = DMODEL * DMODEL / 4;
        conv_f16<<<(o4 + 255) / 256, 256>>>(W_out, wo16, o4);
    }

    // 1) QKV projection (fp16 1-term, 3-stage) -> Q/K/V fp16, [tok][1024]
    tc_gemm_qkv1<<<dim3(QKV_N / 128, MTOK / 128), 256, QGEMM_SMEM>>>(
        x16, wq16, MTOK, QKV_N, DMODEL);

    // 2) Causal flash attention -> fp16 hi/lo output
    flash_attn_tc6<<<dim3(TSEQ / 128, BATCH * NHEADS), 256, ATTN_SMEM>>>(
        Q16, K16, V16, ah, al);

    // 3) Output projection: fp16 2-term A (fp32 out)
    tc_gemm_out<<<dim3(DMODEL / 128, MTOK / 128), 256, OGEMM_SMEM>>>(
        ah, al, wo16, out, MTOK, DMODEL, DMODEL);
}

// round 13
// speedup vs baseline: 2.7553x; 1.0716x over previous
#include <cuda_runtime.h>
#include <cuda_bf16.h>
#include <cuda_fp16.h>
#include <math.h>
#include <stdint.h>

// Problem constants
#define BATCH   4
#define TSEQ    2048
#define DMODEL  1024
#define NHEADS  16
#define DHEAD   64
#define MTOK    (BATCH * TSEQ)       // 8192 rows
#define QKV_N   (3 * DMODEL)         // 3072

// Scratch (no cudaMalloc). Per-token layouts are [tok][1024] (h*64+d).
__device__ __half g_Q16[(size_t)MTOK * DMODEL];
__device__ __half g_K16[(size_t)MTOK * DMODEL];
__device__ __half g_V16[(size_t)MTOK * DMODEL];
__device__ __half g_x16[(size_t)MTOK * DMODEL];
__device__ __half g_wq16[(size_t)DMODEL * QKV_N];
__device__ __half g_wo16[(size_t)DMODEL * DMODEL];
__device__ __half g_ah[(size_t)MTOK * DMODEL];       // attn out fp16 hi
__device__ __half g_al[(size_t)MTOK * DMODEL];       // attn out fp16 lo

// ---------------------------------------------------------------------------
// PTX helpers
// ---------------------------------------------------------------------------
__device__ __forceinline__ uint32_t smem_u32(const void* p) {
    uint32_t a;
    asm("{ .reg .u64 t; cvta.to.shared.u64 t, %1; cvt.u32.u64 %0, t; }"
        : "=r"(a) : "l"(p));
    return a;
}
__device__ __forceinline__ void ldmx4(uint32_t* r, uint32_t addr) {
    asm volatile("ldmatrix.sync.aligned.m8n8.x4.shared.b16 {%0,%1,%2,%3}, [%4];"
                 : "=r"(r[0]), "=r"(r[1]), "=r"(r[2]), "=r"(r[3]) : "r"(addr));
}
__device__ __forceinline__ void ldmx4t(uint32_t* r, uint32_t addr) {
    asm volatile("ldmatrix.sync.aligned.m8n8.x4.trans.shared.b16 {%0,%1,%2,%3}, [%4];"
                 : "=r"(r[0]), "=r"(r[1]), "=r"(r[2]), "=r"(r[3]) : "r"(addr));
}
__device__ __forceinline__ void mma_hf(float* c, const uint32_t* a, const uint32_t* b) {
    asm volatile(
        "mma.sync.aligned.m16n8k16.row.col.f32.f16.f16.f32 "
        "{%0,%1,%2,%3}, {%4,%5,%6,%7}, {%8,%9}, {%0,%1,%2,%3};"
        : "+f"(c[0]), "+f"(c[1]), "+f"(c[2]), "+f"(c[3])
        : "r"(a[0]), "r"(a[1]), "r"(a[2]), "r"(a[3]), "r"(b[0]), "r"(b[1]));
}
__device__ __forceinline__ uint32_t ex2_f16x2(uint32_t x) {
    uint32_t r;
    asm("ex2.approx.f16x2 %0, %1;" : "=r"(r) : "r"(x));
    return r;
}
__device__ __forceinline__ void cpa16(uint32_t dst, const void* src) {
    asm volatile("cp.async.cg.shared.global [%0], [%1], 16;" :: "r"(dst), "l"(src));
}
// SW128 swizzle for 128-byte-pitch rows (attention smem only)
__device__ __forceinline__ uint32_t sw128(int row, int byteoff) {
    return (uint32_t)(row * 128 + (byteoff ^ ((row & 7) << 4)));
}
__device__ __forceinline__ void hfsplit2(float a, float b, uint32_t& hi, uint32_t& lo) {
    __half2 h, l;
    h.x = __float2half_rn(a);
    h.y = __float2half_rn(b);
    l.x = __float2half_rn(a - __half2float(h.x));
    l.y = __float2half_rn(b - __half2float(h.y));
    hi = *(uint32_t*)&h;
    lo = *(uint32_t*)&l;
}

// ---------------------------------------------------------------------------
// fp32 -> fp16 convert
// ---------------------------------------------------------------------------
__global__ __launch_bounds__(256) void conv_f16(
    const float* __restrict__ in, __half* __restrict__ o16, int n4)
{
    int i = blockIdx.x * blockDim.x + threadIdx.x;
    if (i >= n4) return;
    float4 v = ((const float4*)in)[i];
    __half2 a = __floats2half2_rn(v.x, v.y);
    __half2 b = __floats2half2_rn(v.z, v.w);
    ((uint2*)o16)[i] = make_uint2(*(uint32_t*)&a, *(uint32_t*)&b);
}

// ---------------------------------------------------------------------------
// Common GEMM geometry
// ---------------------------------------------------------------------------
#define GPAD_A 40
#define GPAD_B 136
#define STAGE_A (128 * GPAD_A)
#define STAGE_B (32 * GPAD_B)

// ---------------------------------------------------------------------------
// QKV GEMM: single fp16 A-term, 3-stage cp.async pipeline (R12-proven).
// ---------------------------------------------------------------------------
#define QSTAGE_BYTES (STAGE_A * 2 + STAGE_B * 2)       // 18944
#define QGEMM_SMEM (3 * QSTAGE_BYTES)                  // 56832

__global__ __launch_bounds__(256, 2) void tc_gemm_qkv1(
    const __half* __restrict__ Ah, const __half* __restrict__ Bh,
    int M, int N, int K)
{
    extern __shared__ __half smq[];
    const uint32_t smb = smem_u32(smq);

    const int tid  = threadIdx.x;
    const int lane = tid & 31;
    const int wid  = tid >> 5;
    const int wm   = wid & 1;
    const int wn   = wid >> 1;
    const int crow = blockIdx.y * 128;
    const int ccol = blockIdx.x * 128;

    const int arow0 = tid >> 2;
    const int ach   = (tid & 3) * 8;
    const int brow0 = tid >> 4;
    const int bch   = (tid & 15) * 8;

    auto prefetch = [&](int c, int s) {
        const uint32_t sb = smb + (uint32_t)s * QSTAGE_BYTES;
        const size_t ka = (size_t)c * 32;
        #pragma unroll
        for (int j = 0; j < 2; j++) {
            int row = arow0 + j * 64;
            cpa16(sb + (uint32_t)(row * GPAD_A + ach) * 2,
                  Ah + (size_t)(crow + row) * K + ka + ach);
        }
        #pragma unroll
        for (int j = 0; j < 2; j++) {
            int row = brow0 + j * 16;
            cpa16(sb + (uint32_t)(STAGE_A + row * GPAD_B + bch) * 2,
                  Bh + (size_t)(ka + row) * N + ccol + bch);
        }
        asm volatile("cp.async.commit_group;" ::: "memory");
    };

    const int aRowBase = wm * 64 + (lane & 15);
    const int aColOff  = (lane >> 4) * 8;
    const int bKrow    = (lane & 7) + ((lane >> 3) & 1) * 8;
    const int bNBase   = wn * 32 + (lane >> 4) * 8;

    float acc[4][4][4];
    #pragma unroll
    for (int i = 0; i < 4; i++)
        #pragma unroll
        for (int j = 0; j < 4; j++)
            #pragma unroll
            for (int r = 0; r < 4; r++) acc[i][j][r] = 0.f;

    const int nchunks = K >> 5;   // 32
    prefetch(0, 0);
    prefetch(1, 1);

    int s = 0;
    int s2 = 2;
    for (int c = 0; c < nchunks; c++) {
        if (c + 2 < nchunks) {
            prefetch(c + 2, s2);
            asm volatile("cp.async.wait_group 2;" ::: "memory");
        } else if (c + 1 < nchunks) {
            asm volatile("cp.async.wait_group 1;" ::: "memory");
        } else {
            asm volatile("cp.async.wait_group 0;" ::: "memory");
        }
        __syncthreads();

        const uint32_t sb  = smb + (uint32_t)s * QSTAGE_BYTES;
        const uint32_t bAh = sb;
        const uint32_t bBh = sb + STAGE_A * 2;

        #pragma unroll
        for (int ks = 0; ks < 2; ks++) {
            uint32_t ah[4][4], bh[2][4];
            #pragma unroll
            for (int mf = 0; mf < 4; mf++) {
                uint32_t off = (uint32_t)((aRowBase + mf * 16) * GPAD_A + ks * 16 + aColOff) * 2;
                ldmx4(ah[mf], bAh + off);
            }
            #pragma unroll
            for (int nf2 = 0; nf2 < 2; nf2++) {
                uint32_t off = (uint32_t)((ks * 16 + bKrow) * GPAD_B + bNBase + nf2 * 16) * 2;
                ldmx4t(bh[nf2], bBh + off);
            }
            #pragma unroll
            for (int mf = 0; mf < 4; mf++)
                #pragma unroll
                for (int nf = 0; nf < 4; nf++)
                    mma_hf(acc[mf][nf], ah[mf], &bh[nf >> 1][(nf & 1) * 2]);
        }
        __syncthreads();

        s  = (s  == 2) ? 0 : s  + 1;
        s2 = (s2 == 2) ? 0 : s2 + 1;
    }

    const int nbase = ccol + wn * 32;
    const int sect  = nbase >> 10;
    __half* dst = (sect == 0) ? g_Q16 : (sect == 1) ? g_K16 : g_V16;
    #pragma unroll
    for (int mf = 0; mf < 4; mf++) {
        int m0 = crow + wm * 64 + mf * 16 + (lane >> 2);
        #pragma unroll
        for (int nf = 0; nf < 4; nf++) {
            int col = (nbase + nf * 8 + (lane & 3) * 2) & 1023;
            #pragma unroll
            for (int r2 = 0; r2 < 2; r2++) {
                size_t di = (size_t)(m0 + r2 * 8) * 1024 + col;
                __half2 hv = __floats2half2_rn(acc[mf][nf][r2 * 2],
                                               acc[mf][nf][r2 * 2 + 1]);
                *(__half2*)&dst[di] = hv;
            }
        }
    }
}

// ---------------------------------------------------------------------------
// Output GEMM: fp16 2-term A (attn out hi/lo), B fp16 single (R10-proven).
// ---------------------------------------------------------------------------
#define OSTAGE_BYTES (2 * STAGE_A * 2 + STAGE_B * 2)
#define OGEMM_SMEM (2 * OSTAGE_BYTES)

__global__ __launch_bounds__(256, 2) void tc_gemm_out(
    const __half* __restrict__ Ah, const __half* __restrict__ Al,
    const __half* __restrict__ Bh,
    float* __restrict__ C, int M, int N, int K)
{
    extern __shared__ __half smo[];
    const uint32_t smb = smem_u32(smo);

    const int tid  = threadIdx.x;
    const int lane = tid & 31;
    const int wid  = tid >> 5;
    const int wm   = wid & 1;
    const int wn   = wid >> 1;
    const int crow = blockIdx.y * 128;
    const int ccol = blockIdx.x * 128;

    const int arow0 = tid >> 2;
    const int ach   = (tid & 3) * 8;
    const int brow0 = tid >> 4;
    const int bch   = (tid & 15) * 8;

    auto prefetch = [&](int c) {
        const uint32_t sb = smb + (uint32_t)(c & 1) * OSTAGE_BYTES;
        const size_t ka = (size_t)c * 32;
        #pragma unroll
        for (int j = 0; j < 2; j++) {
            int row = arow0 + j * 64;
            const __half* sh = Ah + (size_t)(crow + row) * K + ka + ach;
            const __half* sl = Al + (size_t)(crow + row) * K + ka + ach;
            uint32_t d = sb + (uint32_t)(row * GPAD_A + ach) * 2;
            cpa16(d, sh);
            cpa16(d + STAGE_A * 2, sl);
        }
        #pragma unroll
        for (int j = 0; j < 2; j++) {
            int row = brow0 + j * 16;
            cpa16(sb + (uint32_t)(2 * STAGE_A + row * GPAD_B + bch) * 2,
                  Bh + (size_t)(ka + row) * N + ccol + bch);
        }
        asm volatile("cp.async.commit_group;" ::: "memory");
    };

    const int aRowBase = wm * 64 + (lane & 15);
    const int aColOff  = (lane >> 4) * 8;
    const int bKrow    = (lane & 7) + ((lane >> 3) & 1) * 8;
    const int bNBase   = wn * 32 + (lane >> 4) * 8;

    float acc[4][4][4];
    #pragma unroll
    for (int i = 0; i < 4; i++)
        #pragma unroll
        for (int j = 0; j < 4; j++)
            #pragma unroll
            for (int r = 0; r < 4; r++) acc[i][j][r] = 0.f;

    const int nchunks = K >> 5;
    prefetch(0);

    for (int c = 0; c < nchunks; c++) {
        if (c + 1 < nchunks) {
            prefetch(c + 1);
            asm volatile("cp.async.wait_group 1;" ::: "memory");
        } else {
            asm volatile("cp.async.wait_group 0;" ::: "memory");
        }
        __syncthreads();

        const uint32_t sb  = smb + (uint32_t)(c & 1) * OSTAGE_BYTES;
        const uint32_t bAh = sb;
        const uint32_t bAl = sb + STAGE_A * 2;
        const uint32_t bBh = sb + 2 * STAGE_A * 2;

        #pragma unroll
        for (int ks = 0; ks < 2; ks++) {
            uint32_t ah[4][4], al[4][4], bh[2][4];
            #pragma unroll
            for (int mf = 0; mf < 4; mf++) {
                uint32_t off = (uint32_t)((aRowBase + mf * 16) * GPAD_A + ks * 16 + aColOff) * 2;
                ldmx4(ah[mf], bAh + off);
                ldmx4(al[mf], bAl + off);
            }
            #pragma unroll
            for (int nf2 = 0; nf2 < 2; nf2++) {
                uint32_t off = (uint32_t)((ks * 16 + bKrow) * GPAD_B + bNBase + nf2 * 16) * 2;
                ldmx4t(bh[nf2], bBh + off);
            }
            #pragma unroll
            for (int mf = 0; mf < 4; mf++)
                #pragma unroll
                for (int nf = 0; nf < 4; nf++) {
                    const uint32_t* bhp = &bh[nf >> 1][(nf & 1) * 2];
                    mma_hf(acc[mf][nf], ah[mf], bhp);
                    mma_hf(acc[mf][nf], al[mf], bhp);
                }
        }
        __syncthreads();
    }

    #pragma unroll
    for (int mf = 0; mf < 4; mf++) {
        int row0 = crow + wm * 64 + mf * 16 + (lane >> 2);
        #pragma unroll
        for (int nf = 0; nf < 4; nf++) {
            int col = ccol + wn * 32 + nf * 8 + (lane & 3) * 2;
            *(float2*)&C[(size_t)row0 * N + col] =
                make_float2(acc[mf][nf][0], acc[mf][nf][1]);
            *(float2*)&C[(size_t)(row0 + 8) * N + col] =
                make_float2(acc[mf][nf][2], acc[mf][nf][3]);
        }
    }
}

// ---------------------------------------------------------------------------
// Causal flash attention, all-fp16, kv tiles of 128 with cp.async
// double-buffered KV (proven ordering: prefetch(kt+1) BEFORE wait_group 1).
// smem: Q 16K | 2 x (K 16K + V 16K) = 80 KB, SW128 128B rows.
// Fully-masked kv-halves skipped (numerically exact: exp(-1e5) == 0).
// ---------------------------------------------------------------------------
#define KV_STAGE 32768
#define ATTN_SMEM (16384 + 2 * KV_STAGE)    // 81920

__global__ __launch_bounds__(256, 2) void flash_attn_tc7(
    const __half* __restrict__ Q16, const __half* __restrict__ K16,
    const __half* __restrict__ V16,
    __half* __restrict__ oh, __half* __restrict__ ol)
{
    extern __shared__ char smraw[];
    char* pQ = smraw;
    const uint32_t kvb = smem_u32(smraw + 16384);

    const int tid = threadIdx.x, lane = tid & 31, wid = tid >> 5;
    const int b  = blockIdx.y >> 4;
    const int h  = blockIdx.y & 15;
    const int qt = gridDim.x - 1 - blockIdx.x;   // heavy tiles first
    const int q0 = qt * 128;

    const size_t rbase = (size_t)b * 2048;
    const int    cbase = h * 64;

    auto prefetch_kv = [&](int kt) {
        const int kv0 = kt * 128;
        const uint32_t sb = kvb + (uint32_t)(kt & 1) * KV_STAGE;
        #pragma unroll
        for (int i = 0; i < 4; i++) {
            int li = i * 256 + tid;
            int r = li >> 3, ch = li & 7;
            size_t gi = (rbase + kv0 + r) * 1024 + cbase + ch * 8;
            uint32_t so = sw128(r, ch * 16);
            cpa16(sb + so,         K16 + gi);
            cpa16(sb + 16384 + so, V16 + gi);
        }
        asm volatile("cp.async.commit_group;" ::: "memory");
    };

    prefetch_kv(0);

    // Load Q tile (128 rows x 128B), plain STS (covered by first barrier)
    #pragma unroll
    for (int i = 0; i < 4; i++) {
        int li = i * 256 + tid;
        int r = li >> 3, ch = li & 7;
        size_t gi = (rbase + q0 + r) * 1024 + cbase + ch * 8;
        *(uint4*)(pQ + sw128(r, ch * 16)) = *(const uint4*)(Q16 + gi);
    }

    const uint32_t aQ = smem_u32(pQ);

    const int rowQ = wid * 16 + (lane & 15);
    const int colB = (lane >> 4) * 16;              // bytes
    const int kRow = lane & 15;
    const int vRow = (lane & 7) + ((lane >> 3) & 1) * 8;

    float accO[8][4];
    #pragma unroll
    for (int i = 0; i < 8; i++)
        #pragma unroll
        for (int r = 0; r < 4; r++) accO[i][r] = 0.f;
    float lr = 0.f, lr8 = 0.f;

    const int rowbase = q0 + wid * 16;
    const int nkt = qt + 1;                 // 128-row kv tiles
    const float csc = 0.1803368802f;        // log2(e)/8

    for (int kt = 0; kt < nkt; kt++) {
        if (kt + 1 < nkt) {
            prefetch_kv(kt + 1);
            asm volatile("cp.async.wait_group 1;" ::: "memory");
        } else {
            asm volatile("cp.async.wait_group 0;" ::: "memory");
        }
        __syncthreads();

        const uint32_t sb = kvb + (uint32_t)(kt & 1) * KV_STAGE;
        const uint32_t aK = sb;
        const uint32_t aV = sb + 16384;

        #pragma unroll
        for (int half = 0; half < 2; half++) {
            const int kv0h = kt * 128 + half * 64;
            if (kv0h > rowbase + 15) break;   // fully above diagonal: exact skip
            const int rb = half * 64;          // row offset within 128-row tile

            // --- S = Q K^T (single fp16 term) ---
            float S[8][4];
            #pragma unroll
            for (int i = 0; i < 8; i++)
                #pragma unroll
                for (int r = 0; r < 4; r++) S[i][r] = 0.f;

            #pragma unroll
            for (int ks = 0; ks < 4; ks++) {
                uint32_t aq[4];
                ldmx4(aq, aQ + sw128(rowQ, ks * 32 + colB));
                #pragma unroll
                for (int g = 0; g < 4; g++) {
                    uint32_t kk[4];
                    ldmx4(kk, aK + sw128(rb + g * 16 + kRow, ks * 32 + colB));
                    uint32_t be[2] = {kk[0], kk[2]};
                    uint32_t bo[2] = {kk[1], kk[3]};
                    mma_hf(S[2*g],   aq, be);
                    mma_hf(S[2*g+1], aq, bo);
                }
            }

            // --- causal mask (straddling halves only) ---
            if (kv0h + 63 > rowbase) {
                int r0 = rowbase + (lane >> 2);
                #pragma unroll
                for (int nf = 0; nf < 8; nf++) {
                    int c0 = kv0h + nf * 8 + (lane & 3) * 2;
                    if (c0 > r0)          S[nf][0] = -1e5f;
                    if (c0 + 1 > r0)      S[nf][1] = -1e5f;
                    if (c0 > r0 + 8)      S[nf][2] = -1e5f;
                    if (c0 + 1 > r0 + 8)  S[nf][3] = -1e5f;
                }
            }

            // --- P = exp(S) (fp16 A-frag layout) + row sums ---
            uint32_t P[8][2];
            #pragma unroll
            for (int nf = 0; nf < 8; nf++) {
                __half2 h0 = __floats2half2_rn(S[nf][0] * csc, S[nf][1] * csc);
                __half2 h1 = __floats2half2_rn(S[nf][2] * csc, S[nf][3] * csc);
                uint32_t p0 = ex2_f16x2(*(uint32_t*)&h0);
                uint32_t p1 = ex2_f16x2(*(uint32_t*)&h1);
                P[nf][0] = p0;
                P[nf][1] = p1;
                float2 f0 = __half22float2(*(__half2*)&p0);
                float2 f1 = __half22float2(*(__half2*)&p1);
                lr  += f0.x + f0.y;
                lr8 += f1.x + f1.y;
            }

            // --- O += P @ V ---
            #pragma unroll
            for (int j = 0; j < 4; j++) {
                uint32_t a[4] = { P[2*j][0], P[2*j][1], P[2*j+1][0], P[2*j+1][1] };
                int r = rb + j * 16 + vRow;
                #pragma unroll
                for (int dg = 0; dg < 2; dg++) {
                    uint32_t vv[4], vv2[4];
                    ldmx4t(vv,  aV + sw128(r, dg * 64 + colB));
                    ldmx4t(vv2, aV + sw128(r, dg * 64 + 32 + colB));
                    mma_hf(accO[4*dg + 0], a, &vv[0]);
                    mma_hf(accO[4*dg + 1], a, &vv[2]);
                    mma_hf(accO[4*dg + 2], a, &vv2[0]);
                    mma_hf(accO[4*dg + 3], a, &vv2[2]);
                }
            }
        }
        __syncthreads();
    }

    lr  += __shfl_xor_sync(0xffffffffu, lr, 1);
    lr  += __shfl_xor_sync(0xffffffffu, lr, 2);
    lr8 += __shfl_xor_sync(0xffffffffu, lr8, 1);
    lr8 += __shfl_xor_sync(0xffffffffu, lr8, 2);
    const float inv  = 1.f / lr;
    const float inv8 = 1.f / lr8;

    const int grow = b * TSEQ + q0 + wid * 16 + (lane >> 2);
    #pragma unroll
    for (int dg = 0; dg < 8; dg++) {
        int col = cbase + dg * 8 + (lane & 3) * 2;
        uint32_t hi, lo;
        hfsplit2(accO[dg][0] * inv, accO[dg][1] * inv, hi, lo);
        size_t i0 = (size_t)grow * DMODEL + col;
        *(uint32_t*)&oh[i0] = hi;
        *(uint32_t*)&ol[i0] = lo;
        hfsplit2(accO[dg][2] * inv8, accO[dg][3] * inv8, hi, lo);
        size_t i1 = (size_t)(grow + 8) * DMODEL + col;
        *(uint32_t*)&oh[i1] = hi;
        *(uint32_t*)&ol[i1] = lo;
    }
}

// ---------------------------------------------------------------------------
extern "C" void kernel_launch(void* const* d_in, const int* in_sizes, int n_in,
                              void* d_out, int out_size)
{
    const float* x     = (const float*)d_in[0];
    const float* W_qkv = (const float*)d_in[1];
    const float* W_out = (const float*)d_in[2];
    float* out = (float*)d_out;

    __half *x16, *wq16, *wo16, *ah, *al, *Q16, *K16, *V16;
    cudaGetSymbolAddress((void**)&x16,  g_x16);
    cudaGetSymbolAddress((void**)&wq16, g_wq16);
    cudaGetSymbolAddress((void**)&wo16, g_wo16);
    cudaGetSymbolAddress((void**)&ah,   g_ah);
    cudaGetSymbolAddress((void**)&al,   g_al);
    cudaGetSymbolAddress((void**)&Q16,  g_Q16);
    cudaGetSymbolAddress((void**)&K16,  g_K16);
    cudaGetSymbolAddress((void**)&V16,  g_V16);

    cudaFuncSetAttribute(tc_gemm_qkv1, cudaFuncAttributeMaxDynamicSharedMemorySize,
                         QGEMM_SMEM);
    cudaFuncSetAttribute(tc_gemm_out, cudaFuncAttributeMaxDynamicSharedMemorySize,
                         OGEMM_SMEM);
    cudaFuncSetAttribute(flash_attn_tc7, cudaFuncAttributeMaxDynamicSharedMemorySize,
                         ATTN_SMEM);

    // 0) Convert inputs to fp16
    {
        int n4 = MTOK * DMODEL / 4;
        conv_f16<<<(n4 + 255) / 256, 256>>>(x, x16, n4);
        int w4 = DMODEL * QKV_N / 4;
        conv_f16<<<(w4 + 255) / 256, 256>>>(W_qkv, wq16, w4);
        int o4 = DMODEL * DMODEL / 4;
        conv_f16<<<(o4 + 255) / 256, 256>>>(W_out, wo16, o4);
    }

    // 1) QKV projection (fp16 1-term, 3-stage) -> Q/K/V fp16, [tok][1024]
    tc_gemm_qkv1<<<dim3(QKV_N / 128, MTOK / 128), 256, QGEMM_SMEM>>>(
        x16, wq16, MTOK, QKV_N, DMODEL);

    // 2) Causal flash attention -> fp16 hi/lo output
    flash_attn_tc7<<<dim3(TSEQ / 128, BATCH * NHEADS), 256, ATTN_SMEM>>>(
        Q16, K16, V16, ah, al);

    // 3) Output projection: fp16 2-term A (fp32 out)
    tc_gemm_out<<<dim3(DMODEL / 128, MTOK / 128), 256, OGEMM_SMEM>>>(
        ah, al, wo16, out, MTOK, DMODEL, DMODEL);
}

// round 15
// speedup vs baseline: 2.8629x; 1.0391x over previous
#include <cuda_runtime.h>
#include <cuda_bf16.h>
#include <cuda_fp16.h>
#include <math.h>
#include <stdint.h>

// Problem constants
#define BATCH   4
#define TSEQ    2048
#define DMODEL  1024
#define NHEADS  16
#define DHEAD   64
#define MTOK    (BATCH * TSEQ)       // 8192 rows
#define QKV_N   (3 * DMODEL)         // 3072

// Scratch (no cudaMalloc). Per-token layouts are [tok][1024] (h*64+d).
__device__ __half g_Q16[(size_t)MTOK * DMODEL];
__device__ __half g_K16[(size_t)MTOK * DMODEL];
__device__ __half g_V16[(size_t)MTOK * DMODEL];
__device__ __half g_x16[(size_t)MTOK * DMODEL];
__device__ __half g_wq16[(size_t)DMODEL * QKV_N];
__device__ __half g_wo16[(size_t)DMODEL * DMODEL];
__device__ __half g_a16[(size_t)MTOK * DMODEL];      // attn out fp16

// ---------------------------------------------------------------------------
// PTX helpers
// ---------------------------------------------------------------------------
__device__ __forceinline__ uint32_t smem_u32(const void* p) {
    uint32_t a;
    asm("{ .reg .u64 t; cvta.to.shared.u64 t, %1; cvt.u32.u64 %0, t; }"
        : "=r"(a) : "l"(p));
    return a;
}
__device__ __forceinline__ void ldmx4(uint32_t* r, uint32_t addr) {
    asm volatile("ldmatrix.sync.aligned.m8n8.x4.shared.b16 {%0,%1,%2,%3}, [%4];"
                 : "=r"(r[0]), "=r"(r[1]), "=r"(r[2]), "=r"(r[3]) : "r"(addr));
}
__device__ __forceinline__ void ldmx4t(uint32_t* r, uint32_t addr) {
    asm volatile("ldmatrix.sync.aligned.m8n8.x4.trans.shared.b16 {%0,%1,%2,%3}, [%4];"
                 : "=r"(r[0]), "=r"(r[1]), "=r"(r[2]), "=r"(r[3]) : "r"(addr));
}
__device__ __forceinline__ void mma_hf(float* c, const uint32_t* a, const uint32_t* b) {
    asm volatile(
        "mma.sync.aligned.m16n8k16.row.col.f32.f16.f16.f32 "
        "{%0,%1,%2,%3}, {%4,%5,%6,%7}, {%8,%9}, {%0,%1,%2,%3};"
        : "+f"(c[0]), "+f"(c[1]), "+f"(c[2]), "+f"(c[3])
        : "r"(a[0]), "r"(a[1]), "r"(a[2]), "r"(a[3]), "r"(b[0]), "r"(b[1]));
}
__device__ __forceinline__ uint32_t ex2_f16x2(uint32_t x) {
    uint32_t r;
    asm("ex2.approx.f16x2 %0, %1;" : "=r"(r) : "r"(x));
    return r;
}
__device__ __forceinline__ void cpa16(uint32_t dst, const void* src) {
    asm volatile("cp.async.cg.shared.global [%0], [%1], 16;" :: "r"(dst), "l"(src));
}
// SW128 swizzle for 128-byte-pitch rows (attention smem only)
__device__ __forceinline__ uint32_t sw128(int row, int byteoff) {
    return (uint32_t)(row * 128 + (byteoff ^ ((row & 7) << 4)));
}

// ---------------------------------------------------------------------------
// fp32 -> fp16 convert
// ---------------------------------------------------------------------------
__global__ __launch_bounds__(256) void conv_f16(
    const float* __restrict__ in, __half* __restrict__ o16, int n4)
{
    int i = blockIdx.x * blockDim.x + threadIdx.x;
    if (i >= n4) return;
    float4 v = ((const float4*)in)[i];
    __half2 a = __floats2half2_rn(v.x, v.y);
    __half2 b = __floats2half2_rn(v.z, v.w);
    ((uint2*)o16)[i] = make_uint2(*(uint32_t*)&a, *(uint32_t*)&b);
}

// ---------------------------------------------------------------------------
// GEMM: single fp16 term, CTA 128x128, BK=64, 2-stage cp.async
// (proven ordering: prefetch(c+1) BEFORE wait_group 1; trailing sync).
// A pitch 72 elems (144B rows: phase banks 4i mod 32 distinct — conflict-free).
// MODE 0: qkv epilogue -> g_Q16/K16/V16 ([tok][1024] fp16).
// MODE 1: plain fp32 C.
// ---------------------------------------------------------------------------
#define G2PAD_A 72
#define G2PAD_B 136
#define STAGE_A64 (128 * G2PAD_A)      // 9216 elems
#define STAGE_B64 (64 * G2PAD_B)       // 8704 elems
#define G2STAGE_BYTES ((STAGE_A64 + STAGE_B64) * 2)   // 35840
#define G2_SMEM (2 * G2STAGE_BYTES)                   // 71680

template<int MODE>
__global__ __launch_bounds__(256, 2) void tc_gemm64(
    const __half* __restrict__ Ah, const __half* __restrict__ Bh,
    float* __restrict__ C, int M, int N, int K)
{
    extern __shared__ __half smg[];
    const uint32_t smb = smem_u32(smg);

    const int tid  = threadIdx.x;
    const int lane = tid & 31;
    const int wid  = tid >> 5;
    const int wm   = wid & 1;
    const int wn   = wid >> 1;
    const int crow = blockIdx.y * 128;
    const int ccol = blockIdx.x * 128;

    // cp.async coords: A 128 rows x 8 16B-chunks; B 64 rows x 16 16B-chunks
    const int arow = tid >> 1;                 // 0..127
    const int abc  = (tid & 1) * 4;            // chunk 0..3 or 4..7
    const int brow0 = tid >> 4;                // 0..15 (+16,+32,+48)
    const int bch   = (tid & 15) * 8;          // elems

    auto prefetch = [&](int c) {
        const uint32_t sb = smb + (uint32_t)(c & 1) * G2STAGE_BYTES;
        const size_t ka = (size_t)c * 64;
        const __half* as = Ah + (size_t)(crow + arow) * K + ka;
        #pragma unroll
        for (int j = 0; j < 4; j++) {
            int ch = abc + j;
            cpa16(sb + (uint32_t)(arow * G2PAD_A + ch * 8) * 2, as + ch * 8);
        }
        #pragma unroll
        for (int j = 0; j < 4; j++) {
            int row = brow0 + j * 16;
            cpa16(sb + (uint32_t)(STAGE_A64 + row * G2PAD_B + bch) * 2,
                  Bh + (size_t)(ka + row) * N + ccol + bch);
        }
        asm volatile("cp.async.commit_group;" ::: "memory");
    };

    const int aRowBase = wm * 64 + (lane & 15);
    const int aColOff  = (lane >> 4) * 8;
    const int bKrow    = (lane & 7) + ((lane >> 3) & 1) * 8;
    const int bNBase   = wn * 32 + (lane >> 4) * 8;

    float acc[4][4][4];
    #pragma unroll
    for (int i = 0; i < 4; i++)
        #pragma unroll
        for (int j = 0; j < 4; j++)
            #pragma unroll
            for (int r = 0; r < 4; r++) acc[i][j][r] = 0.f;

    const int nchunks = K >> 6;   // K/64 = 16
    prefetch(0);

    for (int c = 0; c < nchunks; c++) {
        if (c + 1 < nchunks) {
            prefetch(c + 1);
            asm volatile("cp.async.wait_group 1;" ::: "memory");
        } else {
            asm volatile("cp.async.wait_group 0;" ::: "memory");
        }
        __syncthreads();

        const uint32_t sb  = smb + (uint32_t)(c & 1) * G2STAGE_BYTES;
        const uint32_t bAh = sb;
        const uint32_t bBh = sb + STAGE_A64 * 2;

        #pragma unroll
        for (int ks = 0; ks < 4; ks++) {
            uint32_t ah[4][4], bh[2][4];
            #pragma unroll
            for (int mf = 0; mf < 4; mf++) {
                uint32_t off = (uint32_t)((aRowBase + mf * 16) * G2PAD_A + ks * 16 + aColOff) * 2;
                ldmx4(ah[mf], bAh + off);
            }
            #pragma unroll
            for (int nf2 = 0; nf2 < 2; nf2++) {
                uint32_t off = (uint32_t)((ks * 16 + bKrow) * G2PAD_B + bNBase + nf2 * 16) * 2;
                ldmx4t(bh[nf2], bBh + off);
            }
            #pragma unroll
            for (int mf = 0; mf < 4; mf++)
                #pragma unroll
                for (int nf = 0; nf < 4; nf++)
                    mma_hf(acc[mf][nf], ah[mf], &bh[nf >> 1][(nf & 1) * 2]);
        }
        __syncthreads();
    }

    if (MODE == 1) {
        #pragma unroll
        for (int mf = 0; mf < 4; mf++) {
            int row0 = crow + wm * 64 + mf * 16 + (lane >> 2);
            #pragma unroll
            for (int nf = 0; nf < 4; nf++) {
                int col = ccol + wn * 32 + nf * 8 + (lane & 3) * 2;
                *(float2*)&C[(size_t)row0 * N + col] =
                    make_float2(acc[mf][nf][0], acc[mf][nf][1]);
                *(float2*)&C[(size_t)(row0 + 8) * N + col] =
                    make_float2(acc[mf][nf][2], acc[mf][nf][3]);
            }
        }
    } else {
        // qkv epilogue: n -> sect (q/k/v) + col (h*64+d), [tok][1024], fp16
        const int nbase = ccol + wn * 32;
        const int sect  = nbase >> 10;
        __half* dst = (sect == 0) ? g_Q16 : (sect == 1) ? g_K16 : g_V16;
        #pragma unroll
        for (int mf = 0; mf < 4; mf++) {
            int m0 = crow + wm * 64 + mf * 16 + (lane >> 2);
            #pragma unroll
            for (int nf = 0; nf < 4; nf++) {
                int col = (nbase + nf * 8 + (lane & 3) * 2) & 1023;
                #pragma unroll
                for (int r2 = 0; r2 < 2; r2++) {
                    size_t di = (size_t)(m0 + r2 * 8) * 1024 + col;
                    __half2 hv = __floats2half2_rn(acc[mf][nf][r2 * 2],
                                                   acc[mf][nf][r2 * 2 + 1]);
                    *(__half2*)&dst[di] = hv;
                }
            }
        }
    }
}

// ---------------------------------------------------------------------------
// Causal flash attention, all-fp16, kv tiles of 128 with cp.async
// double-buffered KV (R13-proven). Output: single fp16 (g_a16).
// smem: Q 16K | 2 x (K 16K + V 16K) = 80 KB, SW128 128B rows.
// ---------------------------------------------------------------------------
#define KV_STAGE 32768
#define ATTN_SMEM (16384 + 2 * KV_STAGE)    // 81920

__global__ __launch_bounds__(256, 2) void flash_attn_tc8(
    const __half* __restrict__ Q16, const __half* __restrict__ K16,
    const __half* __restrict__ V16,
    __half* __restrict__ o16)
{
    extern __shared__ char smraw[];
    char* pQ = smraw;
    const uint32_t kvb = smem_u32(smraw + 16384);

    const int tid = threadIdx.x, lane = tid & 31, wid = tid >> 5;
    const int b  = blockIdx.y >> 4;
    const int h  = blockIdx.y & 15;
    const int qt = gridDim.x - 1 - blockIdx.x;   // heavy tiles first
    const int q0 = qt * 128;

    const size_t rbase = (size_t)b * 2048;
    const int    cbase = h * 64;

    auto prefetch_kv = [&](int kt) {
        const int kv0 = kt * 128;
        const uint32_t sb = kvb + (uint32_t)(kt & 1) * KV_STAGE;
        #pragma unroll
        for (int i = 0; i < 4; i++) {
            int li = i * 256 + tid;
            int r = li >> 3, ch = li & 7;
            size_t gi = (rbase + kv0 + r) * 1024 + cbase + ch * 8;
            uint32_t so = sw128(r, ch * 16);
            cpa16(sb + so,         K16 + gi);
            cpa16(sb + 16384 + so, V16 + gi);
        }
        asm volatile("cp.async.commit_group;" ::: "memory");
    };

    prefetch_kv(0);

    #pragma unroll
    for (int i = 0; i < 4; i++) {
        int li = i * 256 + tid;
        int r = li >> 3, ch = li & 7;
        size_t gi = (rbase + q0 + r) * 1024 + cbase + ch * 8;
        *(uint4*)(pQ + sw128(r, ch * 16)) = *(const uint4*)(Q16 + gi);
    }

    const uint32_t aQ = smem_u32(pQ);

    const int rowQ = wid * 16 + (lane & 15);
    const int colB = (lane >> 4) * 16;              // bytes
    const int kRow = lane & 15;
    const int vRow = (lane & 7) + ((lane >> 3) & 1) * 8;

    float accO[8][4];
    #pragma unroll
    for (int i = 0; i < 8; i++)
        #pragma unroll
        for (int r = 0; r < 4; r++) accO[i][r] = 0.f;
    float lr = 0.f, lr8 = 0.f;

    const int rowbase = q0 + wid * 16;
    const int nkt = qt + 1;
    const float csc = 0.1803368802f;        // log2(e)/8

    for (int kt = 0; kt < nkt; kt++) {
        if (kt + 1 < nkt) {
            prefetch_kv(kt + 1);
            asm volatile("cp.async.wait_group 1;" ::: "memory");
        } else {
            asm volatile("cp.async.wait_group 0;" ::: "memory");
        }
        __syncthreads();

        const uint32_t sb = kvb + (uint32_t)(kt & 1) * KV_STAGE;
        const uint32_t aK = sb;
        const uint32_t aV = sb + 16384;

        #pragma unroll
        for (int half = 0; half < 2; half++) {
            const int kv0h = kt * 128 + half * 64;
            if (kv0h > rowbase + 15) break;   // fully above diagonal: exact skip
            const int rb = half * 64;

            float S[8][4];
            #pragma unroll
            for (int i = 0; i < 8; i++)
                #pragma unroll
                for (int r = 0; r < 4; r++) S[i][r] = 0.f;

            #pragma unroll
            for (int ks = 0; ks < 4; ks++) {
                uint32_t aq[4];
                ldmx4(aq, aQ + sw128(rowQ, ks * 32 + colB));
                #pragma unroll
                for (int g = 0; g < 4; g++) {
                    uint32_t kk[4];
                    ldmx4(kk, aK + sw128(rb + g * 16 + kRow, ks * 32 + colB));
                    uint32_t be[2] = {kk[0], kk[2]};
                    uint32_t bo[2] = {kk[1], kk[3]};
                    mma_hf(S[2*g],   aq, be);
                    mma_hf(S[2*g+1], aq, bo);
                }
            }

            if (kv0h + 63 > rowbase) {
                int r0 = rowbase + (lane >> 2);
                #pragma unroll
                for (int nf = 0; nf < 8; nf++) {
                    int c0 = kv0h + nf * 8 + (lane & 3) * 2;
                    if (c0 > r0)          S[nf][0] = -1e5f;
                    if (c0 + 1 > r0)      S[nf][1] = -1e5f;
                    if (c0 > r0 + 8)      S[nf][2] = -1e5f;
                    if (c0 + 1 > r0 + 8)  S[nf][3] = -1e5f;
                }
            }

            uint32_t P[8][2];
            #pragma unroll
            for (int nf = 0; nf < 8; nf++) {
                __half2 h0 = __floats2half2_rn(S[nf][0] * csc, S[nf][1] * csc);
                __half2 h1 = __floats2half2_rn(S[nf][2] * csc, S[nf][3] * csc);
                uint32_t p0 = ex2_f16x2(*(uint32_t*)&h0);
                uint32_t p1 = ex2_f16x2(*(uint32_t*)&h1);
                P[nf][0] = p0;
                P[nf][1] = p1;
                float2 f0 = __half22float2(*(__half2*)&p0);
                float2 f1 = __half22float2(*(__half2*)&p1);
                lr  += f0.x + f0.y;
                lr8 += f1.x + f1.y;
            }

            #pragma unroll
            for (int j = 0; j < 4; j++) {
                uint32_t a[4] = { P[2*j][0], P[2*j][1], P[2*j+1][0], P[2*j+1][1] };
                int r = rb + j * 16 + vRow;
                #pragma unroll
                for (int dg = 0; dg < 2; dg++) {
                    uint32_t vv[4], vv2[4];
                    ldmx4t(vv,  aV + sw128(r, dg * 64 + colB));
                    ldmx4t(vv2, aV + sw128(r, dg * 64 + 32 + colB));
                    mma_hf(accO[4*dg + 0], a, &vv[0]);
                    mma_hf(accO[4*dg + 1], a, &vv[2]);
                    mma_hf(accO[4*dg + 2], a, &vv2[0]);
                    mma_hf(accO[4*dg + 3], a, &vv2[2]);
                }
            }
        }
        __syncthreads();
    }

    lr  += __shfl_xor_sync(0xffffffffu, lr, 1);
    lr  += __shfl_xor_sync(0xffffffffu, lr, 2);
    lr8 += __shfl_xor_sync(0xffffffffu, lr8, 1);
    lr8 += __shfl_xor_sync(0xffffffffu, lr8, 2);
    const float inv  = 1.f / lr;
    const float inv8 = 1.f / lr8;

    const int grow = b * TSEQ + q0 + wid * 16 + (lane >> 2);
    #pragma unroll
    for (int dg = 0; dg < 8; dg++) {
        int col = cbase + dg * 8 + (lane & 3) * 2;
        __half2 v0 = __floats2half2_rn(accO[dg][0] * inv,  accO[dg][1] * inv);
        __half2 v1 = __floats2half2_rn(accO[dg][2] * inv8, accO[dg][3] * inv8);
        *(__half2*)&o16[(size_t)grow * DMODEL + col] = v0;
        *(__half2*)&o16[(size_t)(grow + 8) * DMODEL + col] = v1;
    }
}

// ---------------------------------------------------------------------------
extern "C" void kernel_launch(void* const* d_in, const int* in_sizes, int n_in,
                              void* d_out, int out_size)
{
    const float* x     = (const float*)d_in[0];
    const float* W_qkv = (const float*)d_in[1];
    const float* W_out = (const float*)d_in[2];
    float* out = (float*)d_out;

    __half *x16, *wq16, *wo16, *a16, *Q16, *K16, *V16;
    cudaGetSymbolAddress((void**)&x16,  g_x16);
    cudaGetSymbolAddress((void**)&wq16, g_wq16);
    cudaGetSymbolAddress((void**)&wo16, g_wo16);
    cudaGetSymbolAddress((void**)&a16,  g_a16);
    cudaGetSymbolAddress((void**)&Q16,  g_Q16);
    cudaGetSymbolAddress((void**)&K16,  g_K16);
    cudaGetSymbolAddress((void**)&V16,  g_V16);

    cudaFuncSetAttribute(tc_gemm64<0>, cudaFuncAttributeMaxDynamicSharedMemorySize,
                         G2_SMEM);
    cudaFuncSetAttribute(tc_gemm64<1>, cudaFuncAttributeMaxDynamicSharedMemorySize,
                         G2_SMEM);
    cudaFuncSetAttribute(flash_attn_tc8, cudaFuncAttributeMaxDynamicSharedMemorySize,
                         ATTN_SMEM);

    // 0) Convert inputs to fp16
    {
        int n4 = MTOK * DMODEL / 4;
        conv_f16<<<(n4 + 255) / 256, 256>>>(x, x16, n4);
        int w4 = DMODEL * QKV_N / 4;
        conv_f16<<<(w4 + 255) / 256, 256>>>(W_qkv, wq16, w4);
        int o4 = DMODEL * DMODEL / 4;
        conv_f16<<<(o4 + 255) / 256, 256>>>(W_out, wo16, o4);
    }

    // 1) QKV projection (fp16, BK=64) -> Q/K/V fp16, [tok][1024]
    tc_gemm64<0><<<dim3(QKV_N / 128, MTOK / 128), 256, G2_SMEM>>>(
        x16, wq16, nullptr, MTOK, QKV_N, DMODEL);

    // 2) Causal flash attention -> fp16 output
    flash_attn_tc8<<<dim3(TSEQ / 128, BATCH * NHEADS), 256, ATTN_SMEM>>>(
        Q16, K16, V16, a16);

    // 3) Output projection (fp16, BK=64, fp32 out)
    tc_gemm64<1><<<dim3(DMODEL / 128, MTOK / 128), 256, G2_SMEM>>>(
        a16, wo16, out, MTOK, DMODEL, DMODEL);
}

// round 16
// speedup vs baseline: 3.1303x; 1.0934x over previous
#include <cuda_runtime.h>
#include <cuda_bf16.h>
#include <cuda_fp16.h>
#include <math.h>
#include <stdint.h>

// Problem constants
#define BATCH   4
#define TSEQ    2048
#define DMODEL  1024
#define NHEADS  16
#define DHEAD   64
#define MTOK    (BATCH * TSEQ)       // 8192 rows
#define QKV_N   (3 * DMODEL)         // 3072

// Scratch (no cudaMalloc). Per-token layouts are [tok][1024] (h*64+d).
__device__ __half g_Q16[(size_t)MTOK * DMODEL];
__device__ __half g_K16[(size_t)MTOK * DMODEL];
__device__ __half g_V16[(size_t)MTOK * DMODEL];
__device__ __half g_x16[(size_t)MTOK * DMODEL];
__device__ __half g_wq16[(size_t)DMODEL * QKV_N];
__device__ __half g_wo16[(size_t)DMODEL * DMODEL];
__device__ __half g_a16[(size_t)MTOK * DMODEL];      // attn out fp16

// ---------------------------------------------------------------------------
// PTX helpers
// ---------------------------------------------------------------------------
__device__ __forceinline__ uint32_t smem_u32(const void* p) {
    uint32_t a;
    asm("{ .reg .u64 t; cvta.to.shared.u64 t, %1; cvt.u32.u64 %0, t; }"
        : "=r"(a) : "l"(p));
    return a;
}
__device__ __forceinline__ void ldmx4(uint32_t* r, uint32_t addr) {
    asm volatile("ldmatrix.sync.aligned.m8n8.x4.shared.b16 {%0,%1,%2,%3}, [%4];"
                 : "=r"(r[0]), "=r"(r[1]), "=r"(r[2]), "=r"(r[3]) : "r"(addr));
}
__device__ __forceinline__ void ldmx4t(uint32_t* r, uint32_t addr) {
    asm volatile("ldmatrix.sync.aligned.m8n8.x4.trans.shared.b16 {%0,%1,%2,%3}, [%4];"
                 : "=r"(r[0]), "=r"(r[1]), "=r"(r[2]), "=r"(r[3]) : "r"(addr));
}
__device__ __forceinline__ void mma_hf(float* c, const uint32_t* a, const uint32_t* b) {
    asm volatile(
        "mma.sync.aligned.m16n8k16.row.col.f32.f16.f16.f32 "
        "{%0,%1,%2,%3}, {%4,%5,%6,%7}, {%8,%9}, {%0,%1,%2,%3};"
        : "+f"(c[0]), "+f"(c[1]), "+f"(c[2]), "+f"(c[3])
        : "r"(a[0]), "r"(a[1]), "r"(a[2]), "r"(a[3]), "r"(b[0]), "r"(b[1]));
}
__device__ __forceinline__ uint32_t ex2_f16x2(uint32_t x) {
    uint32_t r;
    asm("ex2.approx.f16x2 %0, %1;" : "=r"(r) : "r"(x));
    return r;
}
__device__ __forceinline__ void cpa16(uint32_t dst, const void* src) {
    asm volatile("cp.async.cg.shared.global [%0], [%1], 16;" :: "r"(dst), "l"(src));
}
// SW128 swizzle for 128-byte-pitch rows (attention smem only)
__device__ __forceinline__ uint32_t sw128(int row, int byteoff) {
    return (uint32_t)(row * 128 + (byteoff ^ ((row & 7) << 4)));
}

// ---------------------------------------------------------------------------
// Fused fp32 -> fp16 convert for all three inputs (one launch).
// blocks [0, NB_X) -> x ; [NB_X, NB_X+NB_WQ) -> W_qkv ; rest -> W_out
// ---------------------------------------------------------------------------
#define NB_X  (MTOK * DMODEL / 4 / 256)        // 8192
#define NB_WQ (DMODEL * QKV_N / 4 / 256)       // 3072
#define NB_WO (DMODEL * DMODEL / 4 / 256)      // 1024

__global__ __launch_bounds__(256) void conv_all(
    const float* __restrict__ x, const float* __restrict__ wq,
    const float* __restrict__ wo)
{
    int bid = blockIdx.x;
    const float* in;
    __half* o16;
    int base;
    if (bid < NB_X) {
        in = x;   o16 = g_x16;  base = bid;
    } else if (bid < NB_X + NB_WQ) {
        in = wq;  o16 = g_wq16; base = bid - NB_X;
    } else {
        in = wo;  o16 = g_wo16; base = bid - NB_X - NB_WQ;
    }
    int i = base * 256 + threadIdx.x;
    float4 v = ((const float4*)in)[i];
    __half2 a = __floats2half2_rn(v.x, v.y);
    __half2 b = __floats2half2_rn(v.z, v.w);
    ((uint2*)o16)[i] = make_uint2(*(uint32_t*)&a, *(uint32_t*)&b);
}

// ---------------------------------------------------------------------------
// Common GEMM geometry (BK=32, R12-proven)
// ---------------------------------------------------------------------------
#define GPAD_A 40
#define GPAD_B 136
#define STAGE_A (128 * GPAD_A)
#define STAGE_B (32 * GPAD_B)
#define QSTAGE_BYTES (STAGE_A * 2 + STAGE_B * 2)       // 18944
#define QGEMM_SMEM (3 * QSTAGE_BYTES)                  // 56832

// ---------------------------------------------------------------------------
// GEMM: single fp16 term, CTA 128x128, BK=32, 3-stage cp.async pipeline
// (R12-proven schedule: prefetch(c+2) before wait_group 2; two syncs/chunk).
// MODE 0: qkv epilogue -> g_Q16/K16/V16 ([tok][1024] fp16).
// MODE 1: plain fp32 C.
// ---------------------------------------------------------------------------
template<int MODE>
__global__ __launch_bounds__(256, 2) void tc_gemm32(
    const __half* __restrict__ Ah, const __half* __restrict__ Bh,
    float* __restrict__ C, int M, int N, int K)
{
    extern __shared__ __half smq[];
    const uint32_t smb = smem_u32(smq);

    const int tid  = threadIdx.x;
    const int lane = tid & 31;
    const int wid  = tid >> 5;
    const int wm   = wid & 1;
    const int wn   = wid >> 1;
    const int crow = blockIdx.y * 128;
    const int ccol = blockIdx.x * 128;

    const int arow0 = tid >> 2;
    const int ach   = (tid & 3) * 8;
    const int brow0 = tid >> 4;
    const int bch   = (tid & 15) * 8;

    auto prefetch = [&](int c, int s) {
        const uint32_t sb = smb + (uint32_t)s * QSTAGE_BYTES;
        const size_t ka = (size_t)c * 32;
        #pragma unroll
        for (int j = 0; j < 2; j++) {
            int row = arow0 + j * 64;
            cpa16(sb + (uint32_t)(row * GPAD_A + ach) * 2,
                  Ah + (size_t)(crow + row) * K + ka + ach);
        }
        #pragma unroll
        for (int j = 0; j < 2; j++) {
            int row = brow0 + j * 16;
            cpa16(sb + (uint32_t)(STAGE_A + row * GPAD_B + bch) * 2,
                  Bh + (size_t)(ka + row) * N + ccol + bch);
        }
        asm volatile("cp.async.commit_group;" ::: "memory");
    };

    const int aRowBase = wm * 64 + (lane & 15);
    const int aColOff  = (lane >> 4) * 8;
    const int bKrow    = (lane & 7) + ((lane >> 3) & 1) * 8;
    const int bNBase   = wn * 32 + (lane >> 4) * 8;

    float acc[4][4][4];
    #pragma unroll
    for (int i = 0; i < 4; i++)
        #pragma unroll
        for (int j = 0; j < 4; j++)
            #pragma unroll
            for (int r = 0; r < 4; r++) acc[i][j][r] = 0.f;

    const int nchunks = K >> 5;
    prefetch(0, 0);
    prefetch(1, 1);

    int s = 0;
    int s2 = 2;
    for (int c = 0; c < nchunks; c++) {
        if (c + 2 < nchunks) {
            prefetch(c + 2, s2);
            asm volatile("cp.async.wait_group 2;" ::: "memory");
        } else if (c + 1 < nchunks) {
            asm volatile("cp.async.wait_group 1;" ::: "memory");
        } else {
            asm volatile("cp.async.wait_group 0;" ::: "memory");
        }
        __syncthreads();

        const uint32_t sb  = smb + (uint32_t)s * QSTAGE_BYTES;
        const uint32_t bAh = sb;
        const uint32_t bBh = sb + STAGE_A * 2;

        #pragma unroll
        for (int ks = 0; ks < 2; ks++) {
            uint32_t ah[4][4], bh[2][4];
            #pragma unroll
            for (int mf = 0; mf < 4; mf++) {
                uint32_t off = (uint32_t)((aRowBase + mf * 16) * GPAD_A + ks * 16 + aColOff) * 2;
                ldmx4(ah[mf], bAh + off);
            }
            #pragma unroll
            for (int nf2 = 0; nf2 < 2; nf2++) {
                uint32_t off = (uint32_t)((ks * 16 + bKrow) * GPAD_B + bNBase + nf2 * 16) * 2;
                ldmx4t(bh[nf2], bBh + off);
            }
            #pragma unroll
            for (int mf = 0; mf < 4; mf++)
                #pragma unroll
                for (int nf = 0; nf < 4; nf++)
                    mma_hf(acc[mf][nf], ah[mf], &bh[nf >> 1][(nf & 1) * 2]);
        }
        __syncthreads();

        s  = (s  == 2) ? 0 : s  + 1;
        s2 = (s2 == 2) ? 0 : s2 + 1;
    }

    if (MODE == 1) {
        #pragma unroll
        for (int mf = 0; mf < 4; mf++) {
            int row0 = crow + wm * 64 + mf * 16 + (lane >> 2);
            #pragma unroll
            for (int nf = 0; nf < 4; nf++) {
                int col = ccol + wn * 32 + nf * 8 + (lane & 3) * 2;
                *(float2*)&C[(size_t)row0 * N + col] =
                    make_float2(acc[mf][nf][0], acc[mf][nf][1]);
                *(float2*)&C[(size_t)(row0 + 8) * N + col] =
                    make_float2(acc[mf][nf][2], acc[mf][nf][3]);
            }
        }
    } else {
        // qkv epilogue: n -> sect (q/k/v) + col (h*64+d), [tok][1024], fp16
        const int nbase = ccol + wn * 32;
        const int sect  = nbase >> 10;
        __half* dst = (sect == 0) ? g_Q16 : (sect == 1) ? g_K16 : g_V16;
        #pragma unroll
        for (int mf = 0; mf < 4; mf++) {
            int m0 = crow + wm * 64 + mf * 16 + (lane >> 2);
            #pragma unroll
            for (int nf = 0; nf < 4; nf++) {
                int col = (nbase + nf * 8 + (lane & 3) * 2) & 1023;
                #pragma unroll
                for (int r2 = 0; r2 < 2; r2++) {
                    size_t di = (size_t)(m0 + r2 * 8) * 1024 + col;
                    __half2 hv = __floats2half2_rn(acc[mf][nf][r2 * 2],
                                                   acc[mf][nf][r2 * 2 + 1]);
                    *(__half2*)&dst[di] = hv;
                }
            }
        }
    }
}

// ---------------------------------------------------------------------------
// Causal flash attention, all-fp16, kv tiles of 128, cp.async double-buffered
// KV (R13-proven). Output: single fp16 (g_a16). smem 80 KB.
// ---------------------------------------------------------------------------
#define KV_STAGE 32768
#define ATTN_SMEM (16384 + 2 * KV_STAGE)    // 81920

__global__ __launch_bounds__(256, 2) void flash_attn_tc8(
    const __half* __restrict__ Q16, const __half* __restrict__ K16,
    const __half* __restrict__ V16,
    __half* __restrict__ o16)
{
    extern __shared__ char smraw[];
    char* pQ = smraw;
    const uint32_t kvb = smem_u32(smraw + 16384);

    const int tid = threadIdx.x, lane = tid & 31, wid = tid >> 5;
    const int b  = blockIdx.y >> 4;
    const int h  = blockIdx.y & 15;
    const int qt = gridDim.x - 1 - blockIdx.x;   // heavy tiles first
    const int q0 = qt * 128;

    const size_t rbase = (size_t)b * 2048;
    const int    cbase = h * 64;

    auto prefetch_kv = [&](int kt) {
        const int kv0 = kt * 128;
        const uint32_t sb = kvb + (uint32_t)(kt & 1) * KV_STAGE;
        #pragma unroll
        for (int i = 0; i < 4; i++) {
            int li = i * 256 + tid;
            int r = li >> 3, ch = li & 7;
            size_t gi = (rbase + kv0 + r) * 1024 + cbase + ch * 8;
            uint32_t so = sw128(r, ch * 16);
            cpa16(sb + so,         K16 + gi);
            cpa16(sb + 16384 + so, V16 + gi);
        }
        asm volatile("cp.async.commit_group;" ::: "memory");
    };

    prefetch_kv(0);

    #pragma unroll
    for (int i = 0; i < 4; i++) {
        int li = i * 256 + tid;
        int r = li >> 3, ch = li & 7;
        size_t gi = (rbase + q0 + r) * 1024 + cbase + ch * 8;
        *(uint4*)(pQ + sw128(r, ch * 16)) = *(const uint4*)(Q16 + gi);
    }

    const uint32_t aQ = smem_u32(pQ);

    const int rowQ = wid * 16 + (lane & 15);
    const int colB = (lane >> 4) * 16;              // bytes
    const int kRow = lane & 15;
    const int vRow = (lane & 7) + ((lane >> 3) & 1) * 8;

    float accO[8][4];
    #pragma unroll
    for (int i = 0; i < 8; i++)
        #pragma unroll
        for (int r = 0; r < 4; r++) accO[i][r] = 0.f;
    float lr = 0.f, lr8 = 0.f;

    const int rowbase = q0 + wid * 16;
    const int nkt = qt + 1;
    const float csc = 0.1803368802f;        // log2(e)/8

    for (int kt = 0; kt < nkt; kt++) {
        if (kt + 1 < nkt) {
            prefetch_kv(kt + 1);
            asm volatile("cp.async.wait_group 1;" ::: "memory");
        } else {
            asm volatile("cp.async.wait_group 0;" ::: "memory");
        }
        __syncthreads();

        const uint32_t sb = kvb + (uint32_t)(kt & 1) * KV_STAGE;
        const uint32_t aK = sb;
        const uint32_t aV = sb + 16384;

        #pragma unroll
        for (int half = 0; half < 2; half++) {
            const int kv0h = kt * 128 + half * 64;
            if (kv0h > rowbase + 15) break;   // fully above diagonal: exact skip
            const int rb = half * 64;

            float S[8][4];
            #pragma unroll
            for (int i = 0; i < 8; i++)
                #pragma unroll
                for (int r = 0; r < 4; r++) S[i][r] = 0.f;

            #pragma unroll
            for (int ks = 0; ks < 4; ks++) {
                uint32_t aq[4];
                ldmx4(aq, aQ + sw128(rowQ, ks * 32 + colB));
                #pragma unroll
                for (int g = 0; g < 4; g++) {
                    uint32_t kk[4];
                    ldmx4(kk, aK + sw128(rb + g * 16 + kRow, ks * 32 + colB));
                    uint32_t be[2] = {kk[0], kk[2]};
                    uint32_t bo[2] = {kk[1], kk[3]};
                    mma_hf(S[2*g],   aq, be);
                    mma_hf(S[2*g+1], aq, bo);
                }
            }

            if (kv0h + 63 > rowbase) {
                int r0 = rowbase + (lane >> 2);
                #pragma unroll
                for (int nf = 0; nf < 8; nf++) {
                    int c0 = kv0h + nf * 8 + (lane & 3) * 2;
                    if (c0 > r0)          S[nf][0] = -1e5f;
                    if (c0 + 1 > r0)      S[nf][1] = -1e5f;
                    if (c0 > r0 + 8)      S[nf][2] = -1e5f;
                    if (c0 + 1 > r0 + 8)  S[nf][3] = -1e5f;
                }
            }

            uint32_t P[8][2];
            #pragma unroll
            for (int nf = 0; nf < 8; nf++) {
                __half2 h0 = __floats2half2_rn(S[nf][0] * csc, S[nf][1] * csc);
                __half2 h1 = __floats2half2_rn(S[nf][2] * csc, S[nf][3] * csc);
                uint32_t p0 = ex2_f16x2(*(uint32_t*)&h0);
                uint32_t p1 = ex2_f16x2(*(uint32_t*)&h1);
                P[nf][0] = p0;
                P[nf][1] = p1;
                float2 f0 = __half22float2(*(__half2*)&p0);
                float2 f1 = __half22float2(*(__half2*)&p1);
                lr  += f0.x + f0.y;
                lr8 += f1.x + f1.y;
            }

            #pragma unroll
            for (int j = 0; j < 4; j++) {
                uint32_t a[4] = { P[2*j][0], P[2*j][1], P[2*j+1][0], P[2*j+1][1] };
                int r = rb + j * 16 + vRow;
                #pragma unroll
                for (int dg = 0; dg < 2; dg++) {
                    uint32_t vv[4], vv2[4];
                    ldmx4t(vv,  aV + sw128(r, dg * 64 + colB));
                    ldmx4t(vv2, aV + sw128(r, dg * 64 + 32 + colB));
                    mma_hf(accO[4*dg + 0], a, &vv[0]);
                    mma_hf(accO[4*dg + 1], a, &vv[2]);
                    mma_hf(accO[4*dg + 2], a, &vv2[0]);
                    mma_hf(accO[4*dg + 3], a, &vv2[2]);
                }
            }
        }
        __syncthreads();
    }

    lr  += __shfl_xor_sync(0xffffffffu, lr, 1);
    lr  += __shfl_xor_sync(0xffffffffu, lr, 2);
    lr8 += __shfl_xor_sync(0xffffffffu, lr8, 1);
    lr8 += __shfl_xor_sync(0xffffffffu, lr8, 2);
    const float inv  = 1.f / lr;
    const float inv8 = 1.f / lr8;

    const int grow = b * TSEQ + q0 + wid * 16 + (lane >> 2);
    #pragma unroll
    for (int dg = 0; dg < 8; dg++) {
        int col = cbase + dg * 8 + (lane & 3) * 2;
        __half2 v0 = __floats2half2_rn(accO[dg][0] * inv,  accO[dg][1] * inv);
        __half2 v1 = __floats2half2_rn(accO[dg][2] * inv8, accO[dg][3] * inv8);
        *(__half2*)&o16[(size_t)grow * DMODEL + col] = v0;
        *(__half2*)&o16[(size_t)(grow + 8) * DMODEL + col] = v1;
    }
}

// ---------------------------------------------------------------------------
extern "C" void kernel_launch(void* const* d_in, const int* in_sizes, int n_in,
                              void* d_out, int out_size)
{
    const float* x     = (const float*)d_in[0];
    const float* W_qkv = (const float*)d_in[1];
    const float* W_out = (const float*)d_in[2];
    float* out = (float*)d_out;

    __half *x16, *wq16, *wo16, *a16, *Q16, *K16, *V16;
    cudaGetSymbolAddress((void**)&x16,  g_x16);
    cudaGetSymbolAddress((void**)&wq16, g_wq16);
    cudaGetSymbolAddress((void**)&wo16, g_wo16);
    cudaGetSymbolAddress((void**)&a16,  g_a16);
    cudaGetSymbolAddress((void**)&Q16,  g_Q16);
    cudaGetSymbolAddress((void**)&K16,  g_K16);
    cudaGetSymbolAddress((void**)&V16,  g_V16);

    cudaFuncSetAttribute(tc_gemm32<0>, cudaFuncAttributeMaxDynamicSharedMemorySize,
                         QGEMM_SMEM);
    cudaFuncSetAttribute(tc_gemm32<1>, cudaFuncAttributeMaxDynamicSharedMemorySize,
                         QGEMM_SMEM);
    cudaFuncSetAttribute(flash_attn_tc8, cudaFuncAttributeMaxDynamicSharedMemorySize,
                         ATTN_SMEM);

    // 0) Convert all inputs to fp16 (single launch)
    conv_all<<<NB_X + NB_WQ + NB_WO, 256>>>(x, W_qkv, W_out);

    // 1) QKV projection (fp16, BK=32, 3-stage) -> Q/K/V fp16, [tok][1024]
    tc_gemm32<0><<<dim3(QKV_N / 128, MTOK / 128), 256, QGEMM_SMEM>>>(
        x16, wq16, nullptr, MTOK, QKV_N, DMODEL);

    // 2) Causal flash attention -> fp16 output
    flash_attn_tc8<<<dim3(TSEQ / 128, BATCH * NHEADS), 256, ATTN_SMEM>>>(
        Q16, K16, V16, a16);

    // 3) Output projection (fp16, BK=32, 3-stage, fp32 out)
    tc_gemm32<1><<<dim3(DMODEL / 128, MTOK / 128), 256, QGEMM_SMEM>>>(
        a16, wo16, out, MTOK, DMODEL, DMODEL);
}